// round 2
// baseline (speedup 1.0000x reference)
#include <cuda_runtime.h>
#include <math.h>

#define B_   64
#define P_   16
#define T_   256
#define I_   256
#define H_   512
#define O_   5
#define NCOL 2048            // 4 gates * H
#define M_   (T_*B_)         // 16384 rows (t-major, b-minor)
#define K_   (P_*I_)         // 4096

// Scratch (static __device__ — no allocations allowed)
__device__ float g_pre[(size_t)M_ * NCOL];   // 134 MB gate pre-activations
__device__ float g_h[2][B_*H_];              // ping-pong hidden state
__device__ float g_c[2][B_*H_];              // ping-pong cell state

// ---------------------------------------------------------------------------
// init: zero h0 / c0
// ---------------------------------------------------------------------------
__global__ void init_kernel() {
    int i = blockIdx.x * blockDim.x + threadIdx.x;
    if (i < B_*H_) { g_h[0][i] = 0.f; g_c[0][i] = 0.f; }
}

// ---------------------------------------------------------------------------
// Phase 1: C[m, gate*512+h] = sum_k A[m,k] * W_gate[k,h]
//   A[m,k] = emb[x[b,p,t], i],  m = t*64+b,  k = p*256+i   (idx==0 -> 0, padding)
// Tiles: BM=128, BN=64, BK=16.  256 threads, per-thread 8x4 via f32x2 pairs.
// ---------------------------------------------------------------------------
__global__ __launch_bounds__(256) void pre_gemm_kernel(
    const int*   __restrict__ x,
    const float* __restrict__ emb,
    const float* __restrict__ Wf, const float* __restrict__ Wi,
    const float* __restrict__ Wg, const float* __restrict__ Wo)
{
    __shared__ __align__(16) float  As[16][130];   // [kk][mm], pad 130: conflict-free + 8B-aligned pairs
    __shared__ __align__(16) float2 Bs[16][64];    // W duplicated into both lanes
    __shared__ int sx[128][16];                    // x indices for this row tile

    const int tid = threadIdx.x;
    const int m0  = blockIdx.y * 128;
    const int n0  = blockIdx.x * 64;
    const int gate = n0 >> 9;
    const int h0   = n0 & 511;
    const float* W = (gate == 0) ? Wf : (gate == 1) ? Wi : (gate == 2) ? Wg : Wo;

    // stage x indices: sx[mm][p]
    for (int lin = tid; lin < 2048; lin += 256) {
        int mm = lin >> 4, p = lin & 15;
        int m = m0 + mm;
        int b = m & 63, t = m >> 6;
        sx[mm][p] = x[b*4096 + p*256 + t];
    }
    __syncthreads();

    const int tx = tid & 15;   // -> 4 cols: n0 + tx*4 + c
    const int ty = tid >> 4;   // -> 8 rows: m0 + ty*8 + r

    unsigned long long acc[4][4];
    #pragma unroll
    for (int r = 0; r < 4; r++)
        #pragma unroll
        for (int c = 0; c < 4; c++) acc[r][c] = 0ULL;

    for (int ko = 0; ko < 256; ko++) {
        const int p  = ko >> 4;
        const int i0 = (ko & 15) << 4;
        // A tile: gather 128x16 from embedding
        #pragma unroll
        for (int l = 0; l < 8; l++) {
            int lin = tid + (l << 8);
            int kkk = lin & 15, mm = lin >> 4;
            int idx = sx[mm][p];
            As[kkk][mm] = idx ? __ldg(emb + (size_t)idx * I_ + i0 + kkk) : 0.f;
        }
        // B tile: 16x64, duplicate into float2 lanes
        #pragma unroll
        for (int l = 0; l < 4; l++) {
            int lin = tid + (l << 8);
            int nn = lin & 63, kk = lin >> 6;
            float w = W[(size_t)(ko*16 + kk)*H_ + h0 + nn];
            Bs[kk][nn] = make_float2(w, w);
        }
        __syncthreads();

        #pragma unroll
        for (int kk = 0; kk < 16; kk++) {
            unsigned long long b2[4], a2[4];
            #pragma unroll
            for (int c = 0; c < 4; c++)
                b2[c] = *reinterpret_cast<const unsigned long long*>(&Bs[kk][tx*4 + c]);
            #pragma unroll
            for (int r = 0; r < 4; r++)
                a2[r] = *reinterpret_cast<const unsigned long long*>(&As[kk][ty*8 + r*2]);
            #pragma unroll
            for (int r = 0; r < 4; r++)
                #pragma unroll
                for (int c = 0; c < 4; c++)
                    asm("fma.rn.f32x2 %0, %1, %2, %0;"
                        : "+l"(acc[r][c]) : "l"(a2[r]), "l"(b2[c]));
        }
        __syncthreads();
    }

    #pragma unroll
    for (int r = 0; r < 4; r++)
        #pragma unroll
        for (int c = 0; c < 4; c++) {
            float2 v = *reinterpret_cast<float2*>(&acc[r][c]);
            int m = m0 + ty*8 + r*2;
            int n = n0 + tx*4 + c;
            g_pre[(size_t)m * NCOL + n]       = v.x;
            g_pre[(size_t)(m+1) * NCOL + n]   = v.y;
        }
}

// ---------------------------------------------------------------------------
// Phase 2: one launch per timestep. 128 blocks; block j owns h-cols [4j,4j+4)
// for ALL 4 gates and ALL 64 batches -> pointwise is block-local.
// ---------------------------------------------------------------------------
__global__ __launch_bounds__(256) void lstm_step_kernel(
    int t,
    const float* __restrict__ Wfh, const float* __restrict__ Wih,
    const float* __restrict__ Wgh, const float* __restrict__ Woh,
    const float* __restrict__ bf,  const float* __restrict__ bi,
    const float* __restrict__ bg,  const float* __restrict__ bo)
{
    const int cur = t & 1, nxt = cur ^ 1;
    __shared__ float hs[64][65];   // h_prev chunk [b][kk]
    __shared__ float ws[64][16];   // W chunk [kk][col]  (col = g*4 + hj)
    __shared__ float sg[64][16];   // gate results [b][col]

    const int tid = threadIdx.x;
    const int tx  = tid & 15;           // col: g = tx>>2, hj = tx&3
    const int ty  = tid >> 4;           // batch base; b = ty + 16*r
    const int hc0 = blockIdx.x * 4;
    const int g   = tx >> 2;
    const int hcol = hc0 + (tx & 3);
    const float* Wh = (g == 0) ? Wfh : (g == 1) ? Wih : (g == 2) ? Wgh : Woh;
    const float* hprev = g_h[cur];

    float acc[4] = {0.f, 0.f, 0.f, 0.f};

    for (int k0 = 0; k0 < H_; k0 += 64) {
        #pragma unroll
        for (int l = 0; l < 16; l++) {          // 64x64 h chunk
            int lin = tid + (l << 8);
            int b = lin >> 6, kk = lin & 63;
            hs[b][kk] = hprev[b*H_ + k0 + kk];
        }
        #pragma unroll
        for (int l = 0; l < 4; l++) {           // 64x16 W chunk
            int lin = tid + (l << 8);
            int kk = lin >> 4, c = lin & 15;
            int gg = c >> 2;
            const float* Wp = (gg == 0) ? Wfh : (gg == 1) ? Wih : (gg == 2) ? Wgh : Woh;
            ws[kk][c] = Wp[(k0 + kk)*H_ + hc0 + (c & 3)];
        }
        __syncthreads();
        #pragma unroll 16
        for (int kk = 0; kk < 64; kk++) {
            float w = ws[kk][tx];
            #pragma unroll
            for (int r = 0; r < 4; r++)
                acc[r] += hs[ty + 16*r][kk] * w;
        }
        __syncthreads();
    }
    (void)Wh; (void)hcol;

    #pragma unroll
    for (int r = 0; r < 4; r++) sg[ty + 16*r][tx] = acc[r];
    __syncthreads();

    // pointwise: 256 threads -> (b, hj)
    {
        int b = tid >> 2, j = tid & 3;
        int hc = hc0 + j;
        size_t prow = ((size_t)t * 64 + b) * NCOL;
        float pf = g_pre[prow + 0*H_ + hc] + bf[hc] + sg[b][0  + j];
        float pi = g_pre[prow + 1*H_ + hc] + bi[hc] + sg[b][4  + j];
        float pg = g_pre[prow + 2*H_ + hc] + bg[hc] + sg[b][8  + j];
        float po = g_pre[prow + 3*H_ + hc] + bo[hc] + sg[b][12 + j];
        float f  = 1.f / (1.f + expf(-pf));
        float ii = 1.f / (1.f + expf(-pi));
        float gg = tanhf(pg);
        float oo = 1.f / (1.f + expf(-po));
        float cp = g_c[cur][b*H_ + hc];
        float cn = f * cp + ii * gg;
        float hn = oo * tanhf(cn);
        g_c[nxt][b*H_ + hc] = cn;
        g_h[nxt][b*H_ + hc] = hn;
    }
}

// ---------------------------------------------------------------------------
// Phase 3: out = h_T @ W_lin + b_lin; emit (out, h_t, c_t) concatenated.
// Final state lives in buffer 0 (256 steps -> even parity).
// ---------------------------------------------------------------------------
__global__ void final_kernel(const float* __restrict__ Wlin,
                             const float* __restrict__ blin,
                             float* __restrict__ out)
{
    int b = blockIdx.x;
    int tid = threadIdx.x;  // 512
    const float* h = g_h[0] + b*H_;
    const float* c = g_c[0] + b*H_;
    __shared__ float sh[H_];
    float hv = h[tid];
    sh[tid] = hv;
    out[B_*O_ + b*H_ + tid]          = hv;      // h_t
    out[B_*O_ + B_*H_ + b*H_ + tid]  = c[tid];  // c_t
    __syncthreads();
    if (tid < O_) {
        float s = blin[tid];
        for (int k = 0; k < H_; k++) s += sh[k] * Wlin[k*O_ + tid];
        out[b*O_ + tid] = s;                     // out
    }
}

// ---------------------------------------------------------------------------
extern "C" void kernel_launch(void* const* d_in, const int* in_sizes, int n_in,
                              void* d_out, int out_size)
{
    const int*   x    = (const int*)  d_in[0];
    const float* emb  = (const float*)d_in[1];
    const float* Wfx  = (const float*)d_in[2];
    const float* Wfh  = (const float*)d_in[3];
    const float* bf   = (const float*)d_in[4];
    const float* Wix  = (const float*)d_in[5];
    const float* Wih  = (const float*)d_in[6];
    const float* bi   = (const float*)d_in[7];
    const float* Wgx  = (const float*)d_in[8];
    const float* Wgh  = (const float*)d_in[9];
    const float* bg   = (const float*)d_in[10];
    const float* Wox  = (const float*)d_in[11];
    const float* Woh  = (const float*)d_in[12];
    const float* bo   = (const float*)d_in[13];
    const float* Wlin = (const float*)d_in[14];
    const float* blin = (const float*)d_in[15];
    float* out = (float*)d_out;

    init_kernel<<<(B_*H_ + 255)/256, 256>>>();

    dim3 grid(NCOL/64, M_/128);  // 32 x 128
    pre_gemm_kernel<<<grid, 256>>>(x, emb, Wfx, Wix, Wgx, Wox);

    for (int t = 0; t < T_; t++)
        lstm_step_kernel<<<128, 256>>>(t, Wfh, Wih, Wgh, Woh, bf, bi, bg, bo);

    final_kernel<<<B_, H_>>>(Wlin, blin, out);
}

// round 3
// speedup vs baseline: 1.0100x; 1.0100x over previous
#include <cuda_runtime.h>
#include <math.h>

#define B_   64
#define P_   16
#define T_   256
#define I_   256
#define H_   512
#define O_   5
#define NCOL 2048            // 4 gates * H
#define M_   (T_*B_)         // 16384 rows (t-major, b-minor)
#define K_   (P_*I_)         // 4096
#define NBLK 128             // persistent blocks (<=148 SMs -> co-resident)

// Scratch (static __device__ — no allocations allowed)
__device__ float g_pre[(size_t)M_ * NCOL];    // 134 MB gate pre-activations
__device__ float g_hT[2][H_ * B_];            // transposed hidden state [hcol][b], ping-pong
__device__ float g_cfin[B_ * H_];             // final cell state
__device__ unsigned g_bar_gen;                // grid-barrier generation (monotonic)
__device__ unsigned g_bar_cnt;                // grid-barrier arrival count

// ---------------------------------------------------------------------------
__global__ void init_kernel() {
    int i = blockIdx.x * blockDim.x + threadIdx.x;
    if (i < H_*B_) { g_hT[0][i] = 0.f; g_hT[1][i] = 0.f; }
}

// ---------------------------------------------------------------------------
// Phase 1: C[m, gate*512+h] = sum_k A[m,k] * W_gate[k,h]   (unchanged, ~2.1ms)
// ---------------------------------------------------------------------------
__global__ __launch_bounds__(256) void pre_gemm_kernel(
    const int*   __restrict__ x,
    const float* __restrict__ emb,
    const float* __restrict__ Wf, const float* __restrict__ Wi,
    const float* __restrict__ Wg, const float* __restrict__ Wo)
{
    __shared__ __align__(16) float  As[16][130];
    __shared__ __align__(16) float2 Bs[16][64];
    __shared__ int sx[128][16];

    const int tid = threadIdx.x;
    const int m0  = blockIdx.y * 128;
    const int n0  = blockIdx.x * 64;
    const int gate = n0 >> 9;
    const int h0   = n0 & 511;
    const float* W = (gate == 0) ? Wf : (gate == 1) ? Wi : (gate == 2) ? Wg : Wo;

    for (int lin = tid; lin < 2048; lin += 256) {
        int mm = lin >> 4, p = lin & 15;
        int m = m0 + mm;
        int b = m & 63, t = m >> 6;
        sx[mm][p] = x[b*4096 + p*256 + t];
    }
    __syncthreads();

    const int tx = tid & 15;
    const int ty = tid >> 4;

    unsigned long long acc[4][4];
    #pragma unroll
    for (int r = 0; r < 4; r++)
        #pragma unroll
        for (int c = 0; c < 4; c++) acc[r][c] = 0ULL;

    for (int ko = 0; ko < 256; ko++) {
        const int p  = ko >> 4;
        const int i0 = (ko & 15) << 4;
        #pragma unroll
        for (int l = 0; l < 8; l++) {
            int lin = tid + (l << 8);
            int kkk = lin & 15, mm = lin >> 4;
            int idx = sx[mm][p];
            As[kkk][mm] = idx ? __ldg(emb + (size_t)idx * I_ + i0 + kkk) : 0.f;
        }
        #pragma unroll
        for (int l = 0; l < 4; l++) {
            int lin = tid + (l << 8);
            int nn = lin & 63, kk = lin >> 6;
            float w = W[(size_t)(ko*16 + kk)*H_ + h0 + nn];
            Bs[kk][nn] = make_float2(w, w);
        }
        __syncthreads();

        #pragma unroll
        for (int kk = 0; kk < 16; kk++) {
            unsigned long long b2[4], a2[4];
            #pragma unroll
            for (int c = 0; c < 4; c++)
                b2[c] = *reinterpret_cast<const unsigned long long*>(&Bs[kk][tx*4 + c]);
            #pragma unroll
            for (int r = 0; r < 4; r++)
                a2[r] = *reinterpret_cast<const unsigned long long*>(&As[kk][ty*8 + r*2]);
            #pragma unroll
            for (int r = 0; r < 4; r++)
                #pragma unroll
                for (int c = 0; c < 4; c++)
                    asm("fma.rn.f32x2 %0, %1, %2, %0;"
                        : "+l"(acc[r][c]) : "l"(a2[r]), "l"(b2[c]));
        }
        __syncthreads();
    }

    #pragma unroll
    for (int r = 0; r < 4; r++)
        #pragma unroll
        for (int c = 0; c < 4; c++) {
            float2 v = *reinterpret_cast<float2*>(&acc[r][c]);
            int m = m0 + ty*8 + r*2;
            int n = n0 + tx*4 + c;
            g_pre[(size_t)m * NCOL + n]       = v.x;
            g_pre[(size_t)(m+1) * NCOL + n]   = v.y;
        }
}

// ---------------------------------------------------------------------------
// Phase 2: persistent recurrence kernel — all 256 steps in ONE launch.
// Block j owns h-cols [4j, 4j+4) for all 4 gates (16 output cols) x 64 batches.
// Weights resident in smem for the whole kernel; c resident in registers.
// ---------------------------------------------------------------------------
__device__ __forceinline__ void ffma2(unsigned long long& acc,
                                      unsigned long long a, unsigned long long b) {
    asm("fma.rn.f32x2 %0, %1, %2, %0;" : "+l"(acc) : "l"(a), "l"(b));
}
__device__ __forceinline__ float2 u2f(unsigned long long u) {
    union { unsigned long long u; float2 f; } v; v.u = u; return v.f;
}
__device__ __forceinline__ float sigm(float v) { return 1.f / (1.f + expf(-v)); }

__device__ __forceinline__ void grid_barrier() {
    __threadfence();
    __syncthreads();
    if (threadIdx.x == 0) {
        unsigned gen = *(volatile unsigned*)&g_bar_gen;
        if (atomicAdd(&g_bar_cnt, 1u) == NBLK - 1) {
            atomicExch(&g_bar_cnt, 0u);
            atomicAdd(&g_bar_gen, 1u);
        } else {
            unsigned cur;
            do {
                __nanosleep(64);
                asm volatile("ld.global.acquire.gpu.u32 %0, [%1];"
                             : "=r"(cur) : "l"(&g_bar_gen));
            } while (cur == gen);
        }
        __threadfence();
    }
    __syncthreads();
}

extern __shared__ unsigned long long dyn_smem[];

__global__ __launch_bounds__(256) void lstm_persist_kernel(
    const float* __restrict__ Wfh, const float* __restrict__ Wih,
    const float* __restrict__ Wgh, const float* __restrict__ Woh,
    const float* __restrict__ bf,  const float* __restrict__ bi,
    const float* __restrict__ bg,  const float* __restrict__ bo)
{
    unsigned long long* ws2 = dyn_smem;              // [512][16] dup f32x2 weights (64 KB)
    float* sg = (float*)(dyn_smem + 512*16);         // [64][17] gate exchange

    const int tid = threadIdx.x;
    const int tx  = tid & 15;                        // col: gate = tx>>2, hj = tx&3
    const int ty  = tid >> 4;                        // batch group: b = 4*ty .. 4*ty+3
    const int hc0 = blockIdx.x * 4;

    // Load this block's weight slice ONCE (duplicated into f32x2 lanes)
    for (int idx = tid; idx < 512*16; idx += 256) {
        int k = idx >> 4, c = idx & 15;
        int g = c >> 2;
        const float* Wp = (g == 0) ? Wfh : (g == 1) ? Wih : (g == 2) ? Wgh : Woh;
        float w = Wp[k*H_ + hc0 + (c & 3)];
        float2 w2 = make_float2(w, w);
        ws2[idx] = *reinterpret_cast<unsigned long long*>(&w2);
    }

    // pointwise mapping: thread -> (pb, phc)
    const int pb  = tid >> 2, pj = tid & 3;
    const int phc = hc0 + pj;
    const float bfv = bf[phc], biv = bi[phc], bgv = bg[phc], bov = bo[phc];
    const float* preb = g_pre + (size_t)pb * NCOL + phc;
    float creg = 0.f;

    __syncthreads();

    for (int t = 0; t < T_; t++) {
        const int cur = t & 1, nxt = cur ^ 1;

        // early-issue streaming loads of pre-activations (DRAM latency hidden by GEMV)
        const float* pp = preb + (size_t)t * 64 * NCOL;
        float pf = __ldcs(pp);
        float pi = __ldcs(pp + 512);
        float pg = __ldcs(pp + 1024);
        float po = __ldcs(pp + 1536);

        // GEMV: acc[b] += hT[kk][b] * W[kk][col]  (4 batches/thread via 2x FFMA2)
        const ulonglong2* h2 = reinterpret_cast<const ulonglong2*>(g_hT[cur]);
        unsigned long long acc0 = 0ULL, acc1 = 0ULL, acc2 = 0ULL, acc3 = 0ULL;
        #pragma unroll 8
        for (int kk = 0; kk < 512; kk++) {
            ulonglong2 a = __ldcg(h2 + kk*16 + ty);      // LDG.128: b = 4ty..4ty+3
            unsigned long long w = ws2[kk*16 + tx];       // LDS.64 dup weight
            if (kk & 1) { ffma2(acc2, a.x, w); ffma2(acc3, a.y, w); }
            else        { ffma2(acc0, a.x, w); ffma2(acc1, a.y, w); }
        }
        float2 e0 = u2f(acc0), o0 = u2f(acc2), e1 = u2f(acc1), o1 = u2f(acc3);
        sg[(4*ty + 0)*17 + tx] = e0.x + o0.x;
        sg[(4*ty + 1)*17 + tx] = e0.y + o0.y;
        sg[(4*ty + 2)*17 + tx] = e1.x + o1.x;
        sg[(4*ty + 3)*17 + tx] = e1.y + o1.y;
        __syncthreads();

        // pointwise LSTM cell (c stays in register)
        float f  = sigm(pf + bfv + sg[pb*17 + pj]);
        float ii = sigm(pi + biv + sg[pb*17 + 4 + pj]);
        float gg = tanhf(pg + bgv + sg[pb*17 + 8 + pj]);
        float oo = sigm(po + bov + sg[pb*17 + 12 + pj]);
        float cn = f * creg + ii * gg;
        float hn = oo * tanhf(cn);
        creg = cn;
        __stcg(&g_hT[nxt][phc*64 + pb], hn);

        if (t == T_ - 1) {
            g_cfin[pb*H_ + phc] = cn;
        } else {
            grid_barrier();
        }
    }
}

// ---------------------------------------------------------------------------
// Phase 3: out = h_T @ W_lin + b_lin; emit (out, h_t, c_t).
// Final h lives in g_hT[0] (t=255 writes buffer (255+1)&1 = 0).
// ---------------------------------------------------------------------------
__global__ void final_kernel(const float* __restrict__ Wlin,
                             const float* __restrict__ blin,
                             float* __restrict__ out)
{
    int b = blockIdx.x;
    int tid = threadIdx.x;  // 512
    __shared__ float sh[H_];
    float hv = g_hT[0][tid*64 + b];
    sh[tid] = hv;
    out[B_*O_ + b*H_ + tid]          = hv;                 // h_t
    out[B_*O_ + B_*H_ + b*H_ + tid]  = g_cfin[b*H_ + tid]; // c_t
    __syncthreads();
    if (tid < O_) {
        float s = blin[tid];
        for (int k = 0; k < H_; k++) s += sh[k] * Wlin[k*O_ + tid];
        out[b*O_ + tid] = s;                               // out
    }
}

// ---------------------------------------------------------------------------
extern "C" void kernel_launch(void* const* d_in, const int* in_sizes, int n_in,
                              void* d_out, int out_size)
{
    const int*   x    = (const int*)  d_in[0];
    const float* emb  = (const float*)d_in[1];
    const float* Wfx  = (const float*)d_in[2];
    const float* Wfh  = (const float*)d_in[3];
    const float* bf   = (const float*)d_in[4];
    const float* Wix  = (const float*)d_in[5];
    const float* Wih  = (const float*)d_in[6];
    const float* bi   = (const float*)d_in[7];
    const float* Wgx  = (const float*)d_in[8];
    const float* Wgh  = (const float*)d_in[9];
    const float* bg   = (const float*)d_in[10];
    const float* Wox  = (const float*)d_in[11];
    const float* Woh  = (const float*)d_in[12];
    const float* bo   = (const float*)d_in[13];
    const float* Wlin = (const float*)d_in[14];
    const float* blin = (const float*)d_in[15];
    float* out = (float*)d_out;

    init_kernel<<<(H_*B_ + 255)/256, 256>>>();

    dim3 grid(NCOL/64, M_/128);  // 32 x 128
    pre_gemm_kernel<<<grid, 256>>>(x, emb, Wfx, Wix, Wgx, Wox);

    const int dyn_bytes = 512*16*8 + 64*17*4;   // 65536 + 4352 = 69888
    cudaFuncSetAttribute(lstm_persist_kernel,
                         cudaFuncAttributeMaxDynamicSharedMemorySize, dyn_bytes);
    lstm_persist_kernel<<<NBLK, 256, dyn_bytes>>>(Wfh, Wih, Wgh, Woh, bf, bi, bg, bo);

    final_kernel<<<B_, H_>>>(Wlin, blin, out);
}

// round 4
// speedup vs baseline: 1.1290x; 1.1178x over previous
#include <cuda_runtime.h>
#include <math.h>

#define B_   64
#define P_   16
#define T_   256
#define I_   256
#define H_   512
#define O_   5
#define NCOL 2048            // 4 gates * H
#define M_   (T_*B_)         // 16384 rows (t-major, b-minor)
#define K_   (P_*I_)         // 4096
#define NBLK 128             // persistent blocks (<=148 SMs -> co-resident)

// Scratch (static __device__ — no allocations allowed)
__device__ float g_pre[(size_t)M_ * NCOL];    // 134 MB gate pre-activations
__device__ float g_hT[2][H_ * B_];            // transposed hidden state [hcol][b], ping-pong
__device__ float g_cfin[B_ * H_];             // final cell state
__device__ unsigned g_bar_gen;                // grid-barrier generation (monotonic)
__device__ unsigned g_bar_cnt;                // grid-barrier arrival count

// ---------------------------------------------------------------------------
__global__ void init_kernel() {
    int i = blockIdx.x * blockDim.x + threadIdx.x;
    if (i < H_*B_) { g_hT[0][i] = 0.f; g_hT[1][i] = 0.f; }
}

__device__ __forceinline__ void ffma2(unsigned long long& acc,
                                      unsigned long long a, unsigned long long b) {
    asm("fma.rn.f32x2 %0, %1, %2, %0;" : "+l"(acc) : "l"(a), "l"(b));
}
__device__ __forceinline__ float2 u2f(unsigned long long u) {
    union { unsigned long long u; float2 f; } v; v.u = u; return v.f;
}
__device__ __forceinline__ float sigm(float v) { return 1.f / (1.f + expf(-v)); }

// ---------------------------------------------------------------------------
// Phase 1: C[m, gate*512+h] = sum_k A[m,k] * W_gate[k,h]
//   A[m,k] = emb[x[b,p,t], i],  m = t*64+b,  k = p*256+i   (idx==0 -> 0)
// Tiles: BM=128, BN=64, BK=16.  256 threads.
// Thread tile: rows ty*8..ty*8+7 (4 f32x2 pairs), cols {c*16+tx, c=0..3}.
//   -> b2 LDS.64: 16 consecutive float2 per warp = conflict-free 128B
//   -> a2 via 2x LDS.128 (As row padded to 132 floats, 16B aligned)
// ---------------------------------------------------------------------------
__global__ __launch_bounds__(256) void pre_gemm_kernel(
    const int*   __restrict__ x,
    const float* __restrict__ emb,
    const float* __restrict__ Wf, const float* __restrict__ Wi,
    const float* __restrict__ Wg, const float* __restrict__ Wo)
{
    __shared__ __align__(16) float  As[16][132];   // [kk][mm]
    __shared__ __align__(16) float2 Bs[16][64];    // W duplicated into both lanes
    __shared__ int sx[128][16];

    const int tid = threadIdx.x;
    const int m0  = blockIdx.y * 128;
    const int n0  = blockIdx.x * 64;
    const int gate = n0 >> 9;
    const int h0   = n0 & 511;
    const float* W = (gate == 0) ? Wf : (gate == 1) ? Wi : (gate == 2) ? Wg : Wo;

    for (int lin = tid; lin < 2048; lin += 256) {
        int mm = lin >> 4, p = lin & 15;
        int m = m0 + mm;
        int b = m & 63, t = m >> 6;
        sx[mm][p] = x[b*4096 + p*256 + t];
    }
    __syncthreads();

    const int tx = tid & 15;   // cols: n0 + c*16 + tx
    const int ty = tid >> 4;   // rows: m0 + ty*8 + r

    unsigned long long acc[4][4];
    #pragma unroll
    for (int r = 0; r < 4; r++)
        #pragma unroll
        for (int c = 0; c < 4; c++) acc[r][c] = 0ULL;

    for (int ko = 0; ko < 256; ko++) {
        const int p  = ko >> 4;
        const int i0 = (ko & 15) << 4;
        // A tile: gather 128x16 from embedding
        #pragma unroll
        for (int l = 0; l < 8; l++) {
            int lin = tid + (l << 8);
            int kkk = lin & 15, mm = lin >> 4;
            int idx = sx[mm][p];
            As[kkk][mm] = idx ? __ldg(emb + (size_t)idx * I_ + i0 + kkk) : 0.f;
        }
        // B tile: 16x64, duplicate into float2 lanes
        #pragma unroll
        for (int l = 0; l < 4; l++) {
            int lin = tid + (l << 8);
            int nn = lin & 63, kk = lin >> 6;
            float w = W[(size_t)(ko*16 + kk)*H_ + h0 + nn];
            Bs[kk][nn] = make_float2(w, w);
        }
        __syncthreads();

        #pragma unroll
        for (int kk = 0; kk < 16; kk++) {
            // rows ty*8 .. ty*8+7 as 4 f32x2 pairs via 2x LDS.128
            ulonglong2 a01 = *reinterpret_cast<const ulonglong2*>(&As[kk][ty*8]);
            ulonglong2 a23 = *reinterpret_cast<const ulonglong2*>(&As[kk][ty*8 + 4]);
            unsigned long long b2[4];
            #pragma unroll
            for (int c = 0; c < 4; c++)
                b2[c] = *reinterpret_cast<const unsigned long long*>(&Bs[kk][c*16 + tx]);
            #pragma unroll
            for (int c = 0; c < 4; c++) {
                ffma2(acc[0][c], a01.x, b2[c]);
                ffma2(acc[1][c], a01.y, b2[c]);
                ffma2(acc[2][c], a23.x, b2[c]);
                ffma2(acc[3][c], a23.y, b2[c]);
            }
        }
        __syncthreads();
    }

    #pragma unroll
    for (int r = 0; r < 4; r++)
        #pragma unroll
        for (int c = 0; c < 4; c++) {
            float2 v = u2f(acc[r][c]);
            int m = m0 + ty*8 + r*2;
            int n = n0 + c*16 + tx;          // stride-1 across warp -> coalesced
            __stcs(&g_pre[(size_t)m * NCOL + n],     v.x);
            __stcs(&g_pre[(size_t)(m+1) * NCOL + n], v.y);
        }
}

// ---------------------------------------------------------------------------
// grid barrier for the persistent recurrence kernel
// ---------------------------------------------------------------------------
__device__ __forceinline__ void grid_barrier() {
    __threadfence();
    __syncthreads();
    if (threadIdx.x == 0) {
        unsigned gen = *(volatile unsigned*)&g_bar_gen;
        if (atomicAdd(&g_bar_cnt, 1u) == NBLK - 1) {
            atomicExch(&g_bar_cnt, 0u);
            atomicAdd(&g_bar_gen, 1u);
        } else {
            unsigned cur;
            do {
                __nanosleep(64);
                asm volatile("ld.global.acquire.gpu.u32 %0, [%1];"
                             : "=r"(cur) : "l"(&g_bar_gen));
            } while (cur == gen);
        }
        __threadfence();
    }
    __syncthreads();
}

extern __shared__ unsigned long long dyn_smem[];

// ---------------------------------------------------------------------------
// Phase 2: persistent recurrence kernel — all 256 steps in ONE launch.
// Block j owns h-cols [4j, 4j+4) for all 4 gates x 64 batches.
// Weights resident in smem for the whole kernel; c resident in registers.
// ---------------------------------------------------------------------------
__global__ __launch_bounds__(256) void lstm_persist_kernel(
    const float* __restrict__ Wfh, const float* __restrict__ Wih,
    const float* __restrict__ Wgh, const float* __restrict__ Woh,
    const float* __restrict__ bf,  const float* __restrict__ bi,
    const float* __restrict__ bg,  const float* __restrict__ bo)
{
    unsigned long long* ws2 = dyn_smem;              // [512][16] dup f32x2 weights (64 KB)
    float* sg = (float*)(dyn_smem + 512*16);         // [64][17] gate exchange

    const int tid = threadIdx.x;
    const int tx  = tid & 15;                        // col: gate = tx>>2, hj = tx&3
    const int ty  = tid >> 4;                        // batch group: b = 4*ty .. 4*ty+3
    const int hc0 = blockIdx.x * 4;

    for (int idx = tid; idx < 512*16; idx += 256) {
        int k = idx >> 4, c = idx & 15;
        int g = c >> 2;
        const float* Wp = (g == 0) ? Wfh : (g == 1) ? Wih : (g == 2) ? Wgh : Woh;
        float w = Wp[k*H_ + hc0 + (c & 3)];
        float2 w2 = make_float2(w, w);
        ws2[idx] = *reinterpret_cast<unsigned long long*>(&w2);
    }

    const int pb  = tid >> 2, pj = tid & 3;
    const int phc = hc0 + pj;
    const float bfv = bf[phc], biv = bi[phc], bgv = bg[phc], bov = bo[phc];
    const float* preb = g_pre + (size_t)pb * NCOL + phc;
    float creg = 0.f;

    __syncthreads();

    for (int t = 0; t < T_; t++) {
        const int cur = t & 1, nxt = cur ^ 1;

        const float* pp = preb + (size_t)t * 64 * NCOL;
        float pf = __ldcs(pp);
        float pi = __ldcs(pp + 512);
        float pg = __ldcs(pp + 1024);
        float po = __ldcs(pp + 1536);

        const ulonglong2* h2 = reinterpret_cast<const ulonglong2*>(g_hT[cur]);
        unsigned long long acc0 = 0ULL, acc1 = 0ULL, acc2 = 0ULL, acc3 = 0ULL;
        #pragma unroll 8
        for (int kk = 0; kk < 512; kk++) {
            ulonglong2 a = __ldcg(h2 + kk*16 + ty);      // b = 4ty..4ty+3
            unsigned long long w = ws2[kk*16 + tx];
            if (kk & 1) { ffma2(acc2, a.x, w); ffma2(acc3, a.y, w); }
            else        { ffma2(acc0, a.x, w); ffma2(acc1, a.y, w); }
        }
        float2 e0 = u2f(acc0), o0 = u2f(acc2), e1 = u2f(acc1), o1 = u2f(acc3);
        sg[(4*ty + 0)*17 + tx] = e0.x + o0.x;
        sg[(4*ty + 1)*17 + tx] = e0.y + o0.y;
        sg[(4*ty + 2)*17 + tx] = e1.x + o1.x;
        sg[(4*ty + 3)*17 + tx] = e1.y + o1.y;
        __syncthreads();

        float f  = sigm(pf + bfv + sg[pb*17 + pj]);
        float ii = sigm(pi + biv + sg[pb*17 + 4 + pj]);
        float gg = tanhf(pg + bgv + sg[pb*17 + 8 + pj]);
        float oo = sigm(po + bov + sg[pb*17 + 12 + pj]);
        float cn = f * creg + ii * gg;
        float hn = oo * tanhf(cn);
        creg = cn;
        __stcg(&g_hT[nxt][phc*64 + pb], hn);

        if (t == T_ - 1) {
            g_cfin[pb*H_ + phc] = cn;
        } else {
            grid_barrier();
        }
    }
}

// ---------------------------------------------------------------------------
// Phase 3: out = h_T @ W_lin + b_lin; emit (out, h_t, c_t).
// ---------------------------------------------------------------------------
__global__ void final_kernel(const float* __restrict__ Wlin,
                             const float* __restrict__ blin,
                             float* __restrict__ out)
{
    int b = blockIdx.x;
    int tid = threadIdx.x;  // 512
    __shared__ float sh[H_];
    float hv = g_hT[0][tid*64 + b];
    sh[tid] = hv;
    out[B_*O_ + b*H_ + tid]          = hv;                 // h_t
    out[B_*O_ + B_*H_ + b*H_ + tid]  = g_cfin[b*H_ + tid]; // c_t
    __syncthreads();
    if (tid < O_) {
        float s = blin[tid];
        for (int k = 0; k < H_; k++) s += sh[k] * Wlin[k*O_ + tid];
        out[b*O_ + tid] = s;                               // out
    }
}

// ---------------------------------------------------------------------------
extern "C" void kernel_launch(void* const* d_in, const int* in_sizes, int n_in,
                              void* d_out, int out_size)
{
    const int*   x    = (const int*)  d_in[0];
    const float* emb  = (const float*)d_in[1];
    const float* Wfx  = (const float*)d_in[2];
    const float* Wfh  = (const float*)d_in[3];
    const float* bf   = (const float*)d_in[4];
    const float* Wix  = (const float*)d_in[5];
    const float* Wih  = (const float*)d_in[6];
    const float* bi   = (const float*)d_in[7];
    const float* Wgx  = (const float*)d_in[8];
    const float* Wgh  = (const float*)d_in[9];
    const float* bg   = (const float*)d_in[10];
    const float* Wox  = (const float*)d_in[11];
    const float* Woh  = (const float*)d_in[12];
    const float* bo   = (const float*)d_in[13];
    const float* Wlin = (const float*)d_in[14];
    const float* blin = (const float*)d_in[15];
    float* out = (float*)d_out;

    init_kernel<<<(H_*B_ + 255)/256, 256>>>();

    dim3 grid(NCOL/64, M_/128);  // 32 x 128
    pre_gemm_kernel<<<grid, 256>>>(x, emb, Wfx, Wix, Wgx, Wox);

    const int dyn_bytes = 512*16*8 + 64*17*4;   // 69888
    cudaFuncSetAttribute(lstm_persist_kernel,
                         cudaFuncAttributeMaxDynamicSharedMemorySize, dyn_bytes);
    lstm_persist_kernel<<<NBLK, 256, dyn_bytes>>>(Wfh, Wih, Wgh, Woh, bf, bi, bg, bo);

    final_kernel<<<B_, H_>>>(Wlin, blin, out);
}

// round 6
// speedup vs baseline: 1.3665x; 1.2104x over previous
#include <cuda_runtime.h>
#include <cuda_bf16.h>
#include <cstdint>
#include <stdint.h>
#include <math.h>

#define B_   64
#define P_   16
#define T_   256
#define I_   256
#define H_   512
#define O_   5
#define NCOL 2048            // 4 gates * H
#define M_   (T_*B_)         // 16384 rows (t-major, b-minor)
#define K_   (P_*I_)         // 4096
#define NBLK 128             // persistent blocks for recurrence

#define ASTR 56              // A smem row stride (bf16 elems): 112B, 16B-aligned
#define BSTR 136             // B smem row stride: 272B, 16B-aligned

// Scratch (static __device__ — no allocations allowed)
__device__ float g_pre[(size_t)M_ * NCOL];    // 134 MB gate pre-activations
__device__ float g_hT[2][H_ * B_];            // transposed hidden state [hcol][b]
__device__ float g_cfin[B_ * H_];             // final cell state
__device__ unsigned g_bar_gen;
__device__ unsigned g_bar_cnt;

extern __shared__ char dynsm[];               // shared by both dynamic-smem kernels

// ---------------------------------------------------------------------------
__global__ void init_kernel() {
    int i = blockIdx.x * blockDim.x + threadIdx.x;
    if (i < H_*B_) { g_hT[0][i] = 0.f; g_hT[1][i] = 0.f; }
}

__device__ __forceinline__ void ffma2(unsigned long long& acc,
                                      unsigned long long a, unsigned long long b) {
    asm("fma.rn.f32x2 %0, %1, %2, %0;" : "+l"(acc) : "l"(a), "l"(b));
}
__device__ __forceinline__ float2 u2f(unsigned long long u) {
    union { unsigned long long u; float2 f; } v; v.u = u; return v.f;
}
__device__ __forceinline__ float sigm(float v) { return 1.f / (1.f + expf(-v)); }

__device__ __forceinline__ uint32_t smem_u32(const void* p) {
    return (uint32_t)__cvta_generic_to_shared(p);
}
__device__ __forceinline__ void ldsm_x4(uint32_t* r, uint32_t addr) {
    asm volatile("ldmatrix.sync.aligned.m8n8.x4.shared.b16 {%0,%1,%2,%3}, [%4];"
        : "=r"(r[0]), "=r"(r[1]), "=r"(r[2]), "=r"(r[3]) : "r"(addr));
}
__device__ __forceinline__ void ldsm_x4_t(uint32_t* r, uint32_t addr) {
    asm volatile("ldmatrix.sync.aligned.m8n8.x4.trans.shared.b16 {%0,%1,%2,%3}, [%4];"
        : "=r"(r[0]), "=r"(r[1]), "=r"(r[2]), "=r"(r[3]) : "r"(addr));
}
__device__ __forceinline__ void mma_bf16(float* d, const uint32_t* a,
                                         uint32_t b0, uint32_t b1) {
    asm volatile("mma.sync.aligned.m16n8k16.row.col.f32.bf16.bf16.f32 "
        "{%0,%1,%2,%3}, {%4,%5,%6,%7}, {%8,%9}, {%0,%1,%2,%3};"
        : "+f"(d[0]), "+f"(d[1]), "+f"(d[2]), "+f"(d[3])
        : "r"(a[0]), "r"(a[1]), "r"(a[2]), "r"(a[3]), "r"(b0), "r"(b1));
}
// split fp32 pair -> bf16x2 hi + bf16x2 lo (packed b32, even elem in low half)
__device__ __forceinline__ void cvt2(float x, float y, uint32_t& h, uint32_t& l) {
    __nv_bfloat162 hv, lv;
    hv.x = __float2bfloat16(x);
    hv.y = __float2bfloat16(y);
    lv.x = __float2bfloat16(x - __bfloat162float(hv.x));
    lv.y = __float2bfloat16(y - __bfloat162float(hv.y));
    h = *reinterpret_cast<uint32_t*>(&hv);
    l = *reinterpret_cast<uint32_t*>(&lv);
}

// ---------------------------------------------------------------------------
// Phase 1 (tensor cores): C[m, gate*512+n] = sum_k A[m,k] * W[k,n]
//   A[m,k] = emb[x[b,p,t], i] (fp32, split into bf16 hi/lo),  m=t*64+b, k=p*256+i
// 3-product bf16 split: hh + h*lo + lo*h  (fp32 accum)
// BM=128, BN=128, BK=32; 8 warps, warp tile 64x32 (4 m16 x 4 n8 atoms).
// ---------------------------------------------------------------------------
__global__ __launch_bounds__(256, 1) void pre_gemm_mma(
    const int*   __restrict__ x,
    const float* __restrict__ emb,
    const float* __restrict__ W,     // [K_, 512] for this gate
    int gate, int m_base)
{
    __nv_bfloat16* As_hi = (__nv_bfloat16*)dynsm;          // [128][ASTR]
    __nv_bfloat16* As_lo = As_hi + 128*ASTR;
    __nv_bfloat16* Bs_hi = As_lo + 128*ASTR;               // [32][BSTR]
    __nv_bfloat16* Bs_lo = Bs_hi + 32*BSTR;
    int*           sx    = (int*)(Bs_lo + 32*BSTR);        // [128][16]

    const int tid = threadIdx.x;
    const int m0  = m_base + blockIdx.y * 128;
    const int nb  = blockIdx.x * 128;                       // col offset within gate

    // stage x indices for this row tile
    for (int lin = tid; lin < 2048; lin += 256) {
        int mm = lin >> 4, p = lin & 15;
        int m = m0 + mm;
        sx[mm*16 + p] = x[(m & 63)*4096 + p*256 + (m >> 6)];
    }

    const int w = tid >> 5, lane = tid & 31;
    const int warp_m = (w & 1) * 64;
    const int warp_n = (w >> 1) * 32;

    // A fill mapping: row = w*16 + (lane&15), halves of 32 k-elems by lane>>4
    const int a_row  = w*16 + (lane & 15);
    const int a_half = lane >> 4;
    // B fill mapping: row = (w&3)*8 + (lane>>2), words (w>>2)*32 + (lane&3) + 4j
    const int b_row  = (w & 3)*8 + (lane >> 2);
    const int b_wb   = (w >> 2)*32 + (lane & 3);

    // ldmatrix lane offsets
    const int am_off = lane & 15;
    const int ak_off = (lane >> 4) * 8;
    const int bk_off = ((lane >> 3) & 1)*8 + (lane & 7);
    const int bn_off = ((lane >> 4) & 1)*8;

    float acc[4][4][4];
    #pragma unroll
    for (int mi = 0; mi < 4; mi++)
        #pragma unroll
        for (int nt = 0; nt < 4; nt++)
            #pragma unroll
            for (int e = 0; e < 4; e++) acc[mi][nt][e] = 0.f;

    __syncthreads();

    for (int ko = 0; ko < 128; ko++) {                      // BK=32 chunks
        const int p  = ko >> 3;
        const int i0 = (ko & 7) << 5;

        // ---- A gather + split: 128 rows x 32 fp32 -> bf16 hi/lo
        {
            int idx = sx[a_row*16 + p];
            const float4* src = (const float4*)(emb + (size_t)idx * I_ + i0 + a_half*16);
            __nv_bfloat16* dh = As_hi + a_row*ASTR + a_half*16;
            __nv_bfloat16* dl = As_lo + a_row*ASTR + a_half*16;
            #pragma unroll
            for (int q = 0; q < 4; q++) {
                float4 v = idx ? __ldg(src + q) : make_float4(0.f, 0.f, 0.f, 0.f);
                uint32_t h0, l0, h1, l1;
                cvt2(v.x, v.y, h0, l0);
                cvt2(v.z, v.w, h1, l1);
                *(uint32_t*)(dh + q*4)     = h0;
                *(uint32_t*)(dh + q*4 + 2) = h1;
                *(uint32_t*)(dl + q*4)     = l0;
                *(uint32_t*)(dl + q*4 + 2) = l1;
            }
        }
        // ---- B load + split: 32 rows x 128 fp32
        {
            const float* wr = W + (size_t)(ko*32 + b_row) * H_ + nb;
            __nv_bfloat16* dh = Bs_hi + b_row*BSTR;
            __nv_bfloat16* dl = Bs_lo + b_row*BSTR;
            #pragma unroll
            for (int j = 0; j < 8; j++) {
                int cw = b_wb + 4*j;                         // word (bf16-pair) index
                float2 v = *(const float2*)(wr + 2*cw);
                uint32_t h, l;
                cvt2(v.x, v.y, h, l);
                *(uint32_t*)(dh + 2*cw) = h;
                *(uint32_t*)(dl + 2*cw) = l;
            }
        }
        __syncthreads();

        #pragma unroll
        for (int ks = 0; ks < 2; ks++) {                     // two k16 steps
            uint32_t ah[4][4], bh[8];
            #pragma unroll
            for (int mi = 0; mi < 4; mi++)
                ldsm_x4(ah[mi], smem_u32(As_hi + (warp_m + mi*16 + am_off)*ASTR
                                               + ks*16 + ak_off));
            #pragma unroll
            for (int j2 = 0; j2 < 2; j2++)
                ldsm_x4_t(&bh[j2*4], smem_u32(Bs_hi + (ks*16 + bk_off)*BSTR
                                                    + warp_n + j2*16 + bn_off));
            #pragma unroll
            for (int mi = 0; mi < 4; mi++)
                #pragma unroll
                for (int nt = 0; nt < 4; nt++)
                    mma_bf16(acc[mi][nt], ah[mi], bh[nt*2], bh[nt*2+1]);

            uint32_t bl[8];
            #pragma unroll
            for (int j2 = 0; j2 < 2; j2++)
                ldsm_x4_t(&bl[j2*4], smem_u32(Bs_lo + (ks*16 + bk_off)*BSTR
                                                    + warp_n + j2*16 + bn_off));
            #pragma unroll
            for (int mi = 0; mi < 4; mi++)
                #pragma unroll
                for (int nt = 0; nt < 4; nt++)
                    mma_bf16(acc[mi][nt], ah[mi], bl[nt*2], bl[nt*2+1]);

            uint32_t al[4];
            #pragma unroll
            for (int mi = 0; mi < 4; mi++) {
                ldsm_x4(al, smem_u32(As_lo + (warp_m + mi*16 + am_off)*ASTR
                                           + ks*16 + ak_off));
                #pragma unroll
                for (int nt = 0; nt < 4; nt++)
                    mma_bf16(acc[mi][nt], al, bh[nt*2], bh[nt*2+1]);
            }
        }
        __syncthreads();
    }

    // ---- epilogue: write fp32 to g_pre
    const int er = lane >> 2, ec = (lane & 3)*2;
    #pragma unroll
    for (int mi = 0; mi < 4; mi++)
        #pragma unroll
        for (int nt = 0; nt < 4; nt++) {
            int row = m0 + warp_m + mi*16 + er;
            int col = gate*H_ + nb + warp_n + nt*8 + ec;
            float2 v0 = make_float2(acc[mi][nt][0], acc[mi][nt][1]);
            float2 v1 = make_float2(acc[mi][nt][2], acc[mi][nt][3]);
            __stcs((float2*)&g_pre[(size_t)row * NCOL + col], v0);
            __stcs((float2*)&g_pre[(size_t)(row + 8) * NCOL + col], v1);
        }
}

// ---------------------------------------------------------------------------
// grid barrier for the persistent recurrence kernel
// ---------------------------------------------------------------------------
__device__ __forceinline__ void grid_barrier() {
    __threadfence();
    __syncthreads();
    if (threadIdx.x == 0) {
        unsigned gen = *(volatile unsigned*)&g_bar_gen;
        if (atomicAdd(&g_bar_cnt, 1u) == NBLK - 1) {
            atomicExch(&g_bar_cnt, 0u);
            atomicAdd(&g_bar_gen, 1u);
        } else {
            unsigned cur;
            do {
                __nanosleep(64);
                asm volatile("ld.global.acquire.gpu.u32 %0, [%1];"
                             : "=r"(cur) : "l"(&g_bar_gen));
            } while (cur == gen);
        }
        __threadfence();
    }
    __syncthreads();
}

// ---------------------------------------------------------------------------
// Phase 2: persistent recurrence — all 256 steps in one launch (unchanged)
// ---------------------------------------------------------------------------
__global__ __launch_bounds__(256) void lstm_persist_kernel(
    const float* __restrict__ Wfh, const float* __restrict__ Wih,
    const float* __restrict__ Wgh, const float* __restrict__ Woh,
    const float* __restrict__ bf,  const float* __restrict__ bi,
    const float* __restrict__ bg,  const float* __restrict__ bo)
{
    unsigned long long* ws2 = (unsigned long long*)dynsm;   // [512][16] dup f32x2
    float* sg = (float*)(dynsm + 512*16*8);                 // [64][17]

    const int tid = threadIdx.x;
    const int tx  = tid & 15;
    const int ty  = tid >> 4;
    const int hc0 = blockIdx.x * 4;

    for (int idx = tid; idx < 512*16; idx += 256) {
        int k = idx >> 4, c = idx & 15;
        int g = c >> 2;
        const float* Wp = (g == 0) ? Wfh : (g == 1) ? Wih : (g == 2) ? Wgh : Woh;
        float wv = Wp[k*H_ + hc0 + (c & 3)];
        float2 w2 = make_float2(wv, wv);
        ws2[idx] = *reinterpret_cast<unsigned long long*>(&w2);
    }

    const int pb  = tid >> 2, pj = tid & 3;
    const int phc = hc0 + pj;
    const float bfv = bf[phc], biv = bi[phc], bgv = bg[phc], bov = bo[phc];
    const float* preb = g_pre + (size_t)pb * NCOL + phc;
    float creg = 0.f;

    __syncthreads();

    for (int t = 0; t < T_; t++) {
        const int cur = t & 1, nxt = cur ^ 1;

        const float* pp = preb + (size_t)t * 64 * NCOL;
        float pf = __ldcs(pp);
        float pi = __ldcs(pp + 512);
        float pg = __ldcs(pp + 1024);
        float po = __ldcs(pp + 1536);

        const ulonglong2* h2 = reinterpret_cast<const ulonglong2*>(g_hT[cur]);
        unsigned long long acc0 = 0ULL, acc1 = 0ULL, acc2 = 0ULL, acc3 = 0ULL;
        #pragma unroll 8
        for (int kk = 0; kk < 512; kk++) {
            ulonglong2 a = __ldcg(h2 + kk*16 + ty);
            unsigned long long wv = ws2[kk*16 + tx];
            if (kk & 1) { ffma2(acc2, a.x, wv); ffma2(acc3, a.y, wv); }
            else        { ffma2(acc0, a.x, wv); ffma2(acc1, a.y, wv); }
        }
        float2 e0 = u2f(acc0), o0 = u2f(acc2), e1 = u2f(acc1), o1 = u2f(acc3);
        sg[(4*ty + 0)*17 + tx] = e0.x + o0.x;
        sg[(4*ty + 1)*17 + tx] = e0.y + o0.y;
        sg[(4*ty + 2)*17 + tx] = e1.x + o1.x;
        sg[(4*ty + 3)*17 + tx] = e1.y + o1.y;
        __syncthreads();

        float f  = sigm(pf + bfv + sg[pb*17 + pj]);
        float ii = sigm(pi + biv + sg[pb*17 + 4 + pj]);
        float gg = tanhf(pg + bgv + sg[pb*17 + 8 + pj]);
        float oo = sigm(po + bov + sg[pb*17 + 12 + pj]);
        float cn = f * creg + ii * gg;
        float hn = oo * tanhf(cn);
        creg = cn;
        __stcg(&g_hT[nxt][phc*64 + pb], hn);

        if (t == T_ - 1) {
            g_cfin[pb*H_ + phc] = cn;
        } else {
            grid_barrier();
        }
    }
}

// ---------------------------------------------------------------------------
// Phase 3: out = h_T @ W_lin + b_lin; emit (out, h_t, c_t)
// ---------------------------------------------------------------------------
__global__ void final_kernel(const float* __restrict__ Wlin,
                             const float* __restrict__ blin,
                             float* __restrict__ out)
{
    int b = blockIdx.x;
    int tid = threadIdx.x;  // 512
    __shared__ float sh[H_];
    float hv = g_hT[0][tid*64 + b];
    sh[tid] = hv;
    out[B_*O_ + b*H_ + tid]          = hv;
    out[B_*O_ + B_*H_ + b*H_ + tid]  = g_cfin[b*H_ + tid];
    __syncthreads();
    if (tid < O_) {
        float s = blin[tid];
        for (int k = 0; k < H_; k++) s += sh[k] * Wlin[k*O_ + tid];
        out[b*O_ + tid] = s;
    }
}

// ---------------------------------------------------------------------------
extern "C" void kernel_launch(void* const* d_in, const int* in_sizes, int n_in,
                              void* d_out, int out_size)
{
    const int*   x    = (const int*)  d_in[0];
    const float* emb  = (const float*)d_in[1];
    const float* Wfx  = (const float*)d_in[2];
    const float* Wfh  = (const float*)d_in[3];
    const float* bf   = (const float*)d_in[4];
    const float* Wix  = (const float*)d_in[5];
    const float* Wih  = (const float*)d_in[6];
    const float* bi   = (const float*)d_in[7];
    const float* Wgx  = (const float*)d_in[8];
    const float* Wgh  = (const float*)d_in[9];
    const float* bg   = (const float*)d_in[10];
    const float* Wox  = (const float*)d_in[11];
    const float* Woh  = (const float*)d_in[12];
    const float* bo   = (const float*)d_in[13];
    const float* Wlin = (const float*)d_in[14];
    const float* blin = (const float*)d_in[15];
    float* out = (float*)d_out;

    const int mma_dyn = (128*ASTR*2 + 32*BSTR*2) * 2 + 128*16*4;   // 54272
    cudaFuncSetAttribute(pre_gemm_mma,
                         cudaFuncAttributeMaxDynamicSharedMemorySize, mma_dyn);

    init_kernel<<<(H_*B_ + 255)/256, 256>>>();                       // launch 1

    dim3 gfull(4, 128), ghalf(4, 64);
    pre_gemm_mma<<<gfull, 256, mma_dyn>>>(x, emb, Wfx, 0, 0);        // 2
    pre_gemm_mma<<<gfull, 256, mma_dyn>>>(x, emb, Wix, 1, 0);        // 3
    pre_gemm_mma<<<gfull, 256, mma_dyn>>>(x, emb, Wgx, 2, 0);        // 4
    pre_gemm_mma<<<ghalf, 256, mma_dyn>>>(x, emb, Wox, 3, 0);        // 5
    pre_gemm_mma<<<ghalf, 256, mma_dyn>>>(x, emb, Wox, 3, 8192);     // 6 <- ncu samples this

    const int dyn_bytes = 512*16*8 + 64*17*4;
    cudaFuncSetAttribute(lstm_persist_kernel,
                         cudaFuncAttributeMaxDynamicSharedMemorySize, dyn_bytes);
    lstm_persist_kernel<<<NBLK, 256, dyn_bytes>>>(Wfh, Wih, Wgh, Woh, bf, bi, bg, bo);

    final_kernel<<<B_, H_>>>(Wlin, blin, out);
}

// round 7
// speedup vs baseline: 2.1620x; 1.5821x over previous
#include <cuda_runtime.h>
#include <cuda_bf16.h>
#include <cstdint>
#include <stdint.h>
#include <math.h>

#define B_   64
#define P_   16
#define T_   256
#define I_   256
#define H_   512
#define O_   5
#define NCOL 2048            // 4 gates * H
#define M_   (T_*B_)         // 16384 rows (t-major, b-minor)
#define K_   (P_*I_)         // 4096
#define NBLK 128             // persistent blocks for recurrence

#define ASTR 56              // A smem row stride (bf16 elems)
#define BSTR 136             // B smem row stride

// Scratch (static __device__ — no allocations allowed)
__device__ float g_pre[(size_t)M_ * NCOL];    // 134 MB gate pre-activations
__device__ float g_hT[2][H_ * B_];            // transposed hidden state [hcol][b]
__device__ float g_cfin[B_ * H_];             // final cell state
__device__ unsigned g_bar_gen;
__device__ unsigned g_bar_cnt;

extern __shared__ char dynsm[];               // shared by dynamic-smem kernels

// ---------------------------------------------------------------------------
__global__ void init_kernel() {
    int i = blockIdx.x * blockDim.x + threadIdx.x;
    if (i < H_*B_) { g_hT[0][i] = 0.f; g_hT[1][i] = 0.f; }
}

__device__ __forceinline__ void ffma2(unsigned long long& acc,
                                      unsigned long long a, unsigned long long b) {
    asm("fma.rn.f32x2 %0, %1, %2, %0;" : "+l"(acc) : "l"(a), "l"(b));
}
__device__ __forceinline__ float2 u2f(unsigned long long u) {
    union { unsigned long long u; float2 f; } v; v.u = u; return v.f;
}
__device__ __forceinline__ float sigm(float v) { return 1.f / (1.f + expf(-v)); }

__device__ __forceinline__ uint32_t smem_u32(const void* p) {
    return (uint32_t)__cvta_generic_to_shared(p);
}
__device__ __forceinline__ void ldsm_x4(uint32_t* r, uint32_t addr) {
    asm volatile("ldmatrix.sync.aligned.m8n8.x4.shared.b16 {%0,%1,%2,%3}, [%4];"
        : "=r"(r[0]), "=r"(r[1]), "=r"(r[2]), "=r"(r[3]) : "r"(addr));
}
__device__ __forceinline__ void ldsm_x4_t(uint32_t* r, uint32_t addr) {
    asm volatile("ldmatrix.sync.aligned.m8n8.x4.trans.shared.b16 {%0,%1,%2,%3}, [%4];"
        : "=r"(r[0]), "=r"(r[1]), "=r"(r[2]), "=r"(r[3]) : "r"(addr));
}
__device__ __forceinline__ void mma_bf16(float* d, const uint32_t* a,
                                         uint32_t b0, uint32_t b1) {
    asm volatile("mma.sync.aligned.m16n8k16.row.col.f32.bf16.bf16.f32 "
        "{%0,%1,%2,%3}, {%4,%5,%6,%7}, {%8,%9}, {%0,%1,%2,%3};"
        : "+f"(d[0]), "+f"(d[1]), "+f"(d[2]), "+f"(d[3])
        : "r"(a[0]), "r"(a[1]), "r"(a[2]), "r"(a[3]), "r"(b0), "r"(b1));
}
__device__ __forceinline__ void cvt2(float x, float y, uint32_t& h, uint32_t& l) {
    __nv_bfloat162 hv, lv;
    hv.x = __float2bfloat16(x);
    hv.y = __float2bfloat16(y);
    lv.x = __float2bfloat16(x - __bfloat162float(hv.x));
    lv.y = __float2bfloat16(y - __bfloat162float(hv.y));
    h = *reinterpret_cast<uint32_t*>(&hv);
    l = *reinterpret_cast<uint32_t*>(&lv);
}

// ---------------------------------------------------------------------------
// Phase 1 (tensor cores): unchanged from round 6
// ---------------------------------------------------------------------------
__global__ __launch_bounds__(256, 1) void pre_gemm_mma(
    const int*   __restrict__ x,
    const float* __restrict__ emb,
    const float* __restrict__ W,     // [K_, 512] for this gate
    int gate, int m_base)
{
    __nv_bfloat16* As_hi = (__nv_bfloat16*)dynsm;          // [128][ASTR]
    __nv_bfloat16* As_lo = As_hi + 128*ASTR;
    __nv_bfloat16* Bs_hi = As_lo + 128*ASTR;               // [32][BSTR]
    __nv_bfloat16* Bs_lo = Bs_hi + 32*BSTR;
    int*           sx    = (int*)(Bs_lo + 32*BSTR);        // [128][16]

    const int tid = threadIdx.x;
    const int m0  = m_base + blockIdx.y * 128;
    const int nb  = blockIdx.x * 128;

    for (int lin = tid; lin < 2048; lin += 256) {
        int mm = lin >> 4, p = lin & 15;
        int m = m0 + mm;
        sx[mm*16 + p] = x[(m & 63)*4096 + p*256 + (m >> 6)];
    }

    const int w = tid >> 5, lane = tid & 31;
    const int warp_m = (w & 1) * 64;
    const int warp_n = (w >> 1) * 32;

    const int a_row  = w*16 + (lane & 15);
    const int a_half = lane >> 4;
    const int b_row  = (w & 3)*8 + (lane >> 2);
    const int b_wb   = (w >> 2)*32 + (lane & 3);

    const int am_off = lane & 15;
    const int ak_off = (lane >> 4) * 8;
    const int bk_off = ((lane >> 3) & 1)*8 + (lane & 7);
    const int bn_off = ((lane >> 4) & 1)*8;

    float acc[4][4][4];
    #pragma unroll
    for (int mi = 0; mi < 4; mi++)
        #pragma unroll
        for (int nt = 0; nt < 4; nt++)
            #pragma unroll
            for (int e = 0; e < 4; e++) acc[mi][nt][e] = 0.f;

    __syncthreads();

    for (int ko = 0; ko < 128; ko++) {
        const int p  = ko >> 3;
        const int i0 = (ko & 7) << 5;

        {
            int idx = sx[a_row*16 + p];
            const float4* src = (const float4*)(emb + (size_t)idx * I_ + i0 + a_half*16);
            __nv_bfloat16* dh = As_hi + a_row*ASTR + a_half*16;
            __nv_bfloat16* dl = As_lo + a_row*ASTR + a_half*16;
            #pragma unroll
            for (int q = 0; q < 4; q++) {
                float4 v = idx ? __ldg(src + q) : make_float4(0.f, 0.f, 0.f, 0.f);
                uint32_t h0, l0, h1, l1;
                cvt2(v.x, v.y, h0, l0);
                cvt2(v.z, v.w, h1, l1);
                *(uint32_t*)(dh + q*4)     = h0;
                *(uint32_t*)(dh + q*4 + 2) = h1;
                *(uint32_t*)(dl + q*4)     = l0;
                *(uint32_t*)(dl + q*4 + 2) = l1;
            }
        }
        {
            const float* wr = W + (size_t)(ko*32 + b_row) * H_ + nb;
            __nv_bfloat16* dh = Bs_hi + b_row*BSTR;
            __nv_bfloat16* dl = Bs_lo + b_row*BSTR;
            #pragma unroll
            for (int j = 0; j < 8; j++) {
                int cw = b_wb + 4*j;
                float2 v = *(const float2*)(wr + 2*cw);
                uint32_t h, l;
                cvt2(v.x, v.y, h, l);
                *(uint32_t*)(dh + 2*cw) = h;
                *(uint32_t*)(dl + 2*cw) = l;
            }
        }
        __syncthreads();

        #pragma unroll
        for (int ks = 0; ks < 2; ks++) {
            uint32_t ah[4][4], bh[8];
            #pragma unroll
            for (int mi = 0; mi < 4; mi++)
                ldsm_x4(ah[mi], smem_u32(As_hi + (warp_m + mi*16 + am_off)*ASTR
                                               + ks*16 + ak_off));
            #pragma unroll
            for (int j2 = 0; j2 < 2; j2++)
                ldsm_x4_t(&bh[j2*4], smem_u32(Bs_hi + (ks*16 + bk_off)*BSTR
                                                    + warp_n + j2*16 + bn_off));
            #pragma unroll
            for (int mi = 0; mi < 4; mi++)
                #pragma unroll
                for (int nt = 0; nt < 4; nt++)
                    mma_bf16(acc[mi][nt], ah[mi], bh[nt*2], bh[nt*2+1]);

            uint32_t bl[8];
            #pragma unroll
            for (int j2 = 0; j2 < 2; j2++)
                ldsm_x4_t(&bl[j2*4], smem_u32(Bs_lo + (ks*16 + bk_off)*BSTR
                                                    + warp_n + j2*16 + bn_off));
            #pragma unroll
            for (int mi = 0; mi < 4; mi++)
                #pragma unroll
                for (int nt = 0; nt < 4; nt++)
                    mma_bf16(acc[mi][nt], ah[mi], bl[nt*2], bl[nt*2+1]);

            uint32_t al[4];
            #pragma unroll
            for (int mi = 0; mi < 4; mi++) {
                ldsm_x4(al, smem_u32(As_lo + (warp_m + mi*16 + am_off)*ASTR
                                           + ks*16 + ak_off));
                #pragma unroll
                for (int nt = 0; nt < 4; nt++)
                    mma_bf16(acc[mi][nt], al, bh[nt*2], bh[nt*2+1]);
            }
        }
        __syncthreads();
    }

    const int er = lane >> 2, ec = (lane & 3)*2;
    #pragma unroll
    for (int mi = 0; mi < 4; mi++)
        #pragma unroll
        for (int nt = 0; nt < 4; nt++) {
            int row = m0 + warp_m + mi*16 + er;
            int col = gate*H_ + nb + warp_n + nt*8 + ec;
            float2 v0 = make_float2(acc[mi][nt][0], acc[mi][nt][1]);
            float2 v1 = make_float2(acc[mi][nt][2], acc[mi][nt][3]);
            __stcs((float2*)&g_pre[(size_t)row * NCOL + col], v0);
            __stcs((float2*)&g_pre[(size_t)(row + 8) * NCOL + col], v1);
        }
}

// ---------------------------------------------------------------------------
// grid barrier (128 blocks co-resident)
// ---------------------------------------------------------------------------
__device__ __forceinline__ void grid_barrier() {
    __threadfence();
    __syncthreads();
    if (threadIdx.x == 0) {
        unsigned gen = *(volatile unsigned*)&g_bar_gen;
        if (atomicAdd(&g_bar_cnt, 1u) == NBLK - 1) {
            atomicExch(&g_bar_cnt, 0u);
            atomicAdd(&g_bar_gen, 1u);
        } else {
            unsigned cur;
            do {
                __nanosleep(64);
                asm volatile("ld.global.acquire.gpu.u32 %0, [%1];"
                             : "=r"(cur) : "l"(&g_bar_gen));
            } while (cur == gen);
        }
        __threadfence();
    }
    __syncthreads();
}

// ---------------------------------------------------------------------------
// Phase 2: persistent recurrence — 512 threads/block, k-split halves,
// h staged into smem chunks with explicit MLP; weights smem-resident.
// Block j owns h-cols [4j,4j+4) x 4 gates x 64 batches.
// smem: ws2 64KB | hbuf 4x32KB | sg 2x(64x17)f  = ~200KB, 1 block/SM.
// ---------------------------------------------------------------------------
__global__ __launch_bounds__(512, 1) void lstm_persist_kernel(
    const float* __restrict__ Wfh, const float* __restrict__ Wih,
    const float* __restrict__ Wgh, const float* __restrict__ Woh,
    const float* __restrict__ bf,  const float* __restrict__ bi,
    const float* __restrict__ bg,  const float* __restrict__ bo)
{
    unsigned long long* ws2 = (unsigned long long*)dynsm;       // [512][16] dup f32x2
    float4* hbuf = (float4*)(dynsm + 65536);                    // 4 x [2048] float4
    float*  sg   = (float*)(dynsm + 65536 + 131072);            // 2 x [64][17]

    const int tid  = threadIdx.x;
    const int kh   = tid >> 8;          // k-half: 0 -> k[0,256), 1 -> k[256,512)
    const int stid = tid & 255;
    const int tx   = stid & 15;         // col: gate = tx>>2, hj = tx&3
    const int ty   = stid >> 4;         // batch group: b = 4*ty .. 4*ty+3
    const int hc0  = blockIdx.x * 4;

    // Load this block's weight slice ONCE (duplicated into f32x2 lanes)
    for (int idx = tid; idx < 512*16; idx += 512) {
        int k = idx >> 4, c = idx & 15;
        int g = c >> 2;
        const float* Wp = (g == 0) ? Wfh : (g == 1) ? Wih : (g == 2) ? Wgh : Woh;
        float wv = Wp[k*H_ + hc0 + (c & 3)];
        float2 w2 = make_float2(wv, wv);
        ws2[idx] = *reinterpret_cast<unsigned long long*>(&w2);
    }

    const int pb  = stid >> 2, pj = stid & 3;
    const int phc = hc0 + pj;
    const float bfv = bf[phc], biv = bi[phc], bgv = bg[phc], bov = bo[phc];
    const float* preb = g_pre + (size_t)pb * NCOL + phc;
    float creg = 0.f;

    __syncthreads();

    for (int t = 0; t < T_; t++) {
        const int cur = t & 1, nxt = cur ^ 1;

        // streaming pre-activation loads (DRAM; hidden under the GEMV)
        float pf, pi, pg, po;
        if (kh == 0) {
            const float* pp = preb + (size_t)t * 64 * NCOL;
            pf = __ldcs(pp);
            pi = __ldcs(pp + 512);
            pg = __ldcs(pp + 1024);
            po = __ldcs(pp + 1536);
        }

        const float4* h4 = (const float4*)g_hT[cur];   // 8192 float4 total
        unsigned long long acc0 = 0ULL, acc1 = 0ULL, acc2 = 0ULL, acc3 = 0ULL;

        // prefetch first chunk of this half (8 x float4, back-to-back LDGs)
        float4 r[8];
        {
            const float4* src = h4 + (kh*2) * 2048 + stid;
            #pragma unroll
            for (int q = 0; q < 8; q++) r[q] = __ldcg(src + q*256);
        }

        #pragma unroll
        for (int cc = 0; cc < 2; cc++) {
            const int c = kh*2 + cc;
            float4* buf = hbuf + (size_t)(kh*2 + cc) * 2048;
            #pragma unroll
            for (int q = 0; q < 8; q++) buf[stid + q*256] = r[q];
            __syncthreads();
            if (cc == 0) {
                const float4* src = h4 + (kh*2 + 1) * 2048 + stid;
                #pragma unroll
                for (int q = 0; q < 8; q++) r[q] = __ldcg(src + q*256);
            }
            const ulonglong2* hb = (const ulonglong2*)buf;
            const unsigned long long* wsb = ws2 + (size_t)c * 128 * 16;
            #pragma unroll 8
            for (int kk = 0; kk < 128; kk++) {
                ulonglong2 a = hb[kk*16 + ty];
                unsigned long long wv = wsb[kk*16 + tx];
                if (kk & 1) { ffma2(acc2, a.x, wv); ffma2(acc3, a.y, wv); }
                else        { ffma2(acc0, a.x, wv); ffma2(acc1, a.y, wv); }
            }
            __syncthreads();
        }

        float2 e0 = u2f(acc0), o0 = u2f(acc2), e1 = u2f(acc1), o1 = u2f(acc3);
        float* sgh = sg + kh * (64*17);
        sgh[(4*ty + 0)*17 + tx] = e0.x + o0.x;
        sgh[(4*ty + 1)*17 + tx] = e0.y + o0.y;
        sgh[(4*ty + 2)*17 + tx] = e1.x + o1.x;
        sgh[(4*ty + 3)*17 + tx] = e1.y + o1.y;
        __syncthreads();

        if (kh == 0) {
            float f  = sigm(pf + bfv + sg[pb*17 + pj]        + sg[64*17 + pb*17 + pj]);
            float ii = sigm(pi + biv + sg[pb*17 + 4 + pj]    + sg[64*17 + pb*17 + 4 + pj]);
            float gg = tanhf(pg + bgv + sg[pb*17 + 8 + pj]   + sg[64*17 + pb*17 + 8 + pj]);
            float oo = sigm(po + bov + sg[pb*17 + 12 + pj]   + sg[64*17 + pb*17 + 12 + pj]);
            float cn = f * creg + ii * gg;
            float hn = oo * tanhf(cn);
            creg = cn;
            __stcg(&g_hT[nxt][phc*64 + pb], hn);
            if (t == T_ - 1) g_cfin[pb*H_ + phc] = cn;
        }

        if (t < T_ - 1) grid_barrier();
    }
}

// ---------------------------------------------------------------------------
// Phase 3: out = h_T @ W_lin + b_lin; emit (out, h_t, c_t)
// ---------------------------------------------------------------------------
__global__ void final_kernel(const float* __restrict__ Wlin,
                             const float* __restrict__ blin,
                             float* __restrict__ out)
{
    int b = blockIdx.x;
    int tid = threadIdx.x;  // 512
    __shared__ float sh[H_];
    float hv = g_hT[0][tid*64 + b];
    sh[tid] = hv;
    out[B_*O_ + b*H_ + tid]          = hv;
    out[B_*O_ + B_*H_ + b*H_ + tid]  = g_cfin[b*H_ + tid];
    __syncthreads();
    if (tid < O_) {
        float s = blin[tid];
        for (int k = 0; k < H_; k++) s += sh[k] * Wlin[k*O_ + tid];
        out[b*O_ + tid] = s;
    }
}

// ---------------------------------------------------------------------------
extern "C" void kernel_launch(void* const* d_in, const int* in_sizes, int n_in,
                              void* d_out, int out_size)
{
    const int*   x    = (const int*)  d_in[0];
    const float* emb  = (const float*)d_in[1];
    const float* Wfx  = (const float*)d_in[2];
    const float* Wfh  = (const float*)d_in[3];
    const float* bf   = (const float*)d_in[4];
    const float* Wix  = (const float*)d_in[5];
    const float* Wih  = (const float*)d_in[6];
    const float* bi   = (const float*)d_in[7];
    const float* Wgx  = (const float*)d_in[8];
    const float* Wgh  = (const float*)d_in[9];
    const float* bg   = (const float*)d_in[10];
    const float* Wox  = (const float*)d_in[11];
    const float* Woh  = (const float*)d_in[12];
    const float* bo   = (const float*)d_in[13];
    const float* Wlin = (const float*)d_in[14];
    const float* blin = (const float*)d_in[15];
    float* out = (float*)d_out;

    const int mma_dyn = (128*ASTR*2 + 32*BSTR*2) * 2 + 128*16*4;   // 54272
    cudaFuncSetAttribute(pre_gemm_mma,
                         cudaFuncAttributeMaxDynamicSharedMemorySize, mma_dyn);

    init_kernel<<<(H_*B_ + 255)/256, 256>>>();

    dim3 gfull(4, 128), ghalf(4, 64);
    pre_gemm_mma<<<gfull, 256, mma_dyn>>>(x, emb, Wfx, 0, 0);
    pre_gemm_mma<<<gfull, 256, mma_dyn>>>(x, emb, Wix, 1, 0);
    pre_gemm_mma<<<gfull, 256, mma_dyn>>>(x, emb, Wgx, 2, 0);
    pre_gemm_mma<<<ghalf, 256, mma_dyn>>>(x, emb, Wox, 3, 0);
    pre_gemm_mma<<<ghalf, 256, mma_dyn>>>(x, emb, Wox, 3, 8192);

    const int lstm_dyn = 65536 + 131072 + 2*(64*17)*4;   // 205280 -> pad
    cudaFuncSetAttribute(lstm_persist_kernel,
                         cudaFuncAttributeMaxDynamicSharedMemorySize, 205312);
    lstm_persist_kernel<<<NBLK, 512, 205312>>>(Wfh, Wih, Wgh, Woh, bf, bi, bg, bo);
    (void)lstm_dyn;

    final_kernel<<<B_, H_>>>(Wlin, blin, out);
}

// round 8
// speedup vs baseline: 3.7360x; 1.7281x over previous
#include <cuda_runtime.h>
#include <cuda_bf16.h>
#include <cstdint>
#include <stdint.h>
#include <math.h>

#define B_   64
#define P_   16
#define T_   256
#define I_   256
#define H_   512
#define O_   5
#define NCOL 2048            // 4 gates * H
#define M_   (T_*B_)         // 16384 rows (t-major, b-minor)
#define K_   (P_*I_)         // 4096
#define NBLK 128             // persistent blocks for recurrence

#define ASTR 56              // A smem row stride (bf16 elems)
#define BSTR 136             // B smem row stride

// Scratch (static __device__ — no allocations allowed)
__device__ float g_pre[(size_t)M_ * NCOL];    // 134 MB gate pre-activations
__device__ float g_hT[2][H_ * B_];            // transposed hidden state [hcol][b]
__device__ float g_cfin[B_ * H_];             // final cell state
__device__ unsigned g_bar_gen;
__device__ unsigned g_bar_cnt;

extern __shared__ char dynsm[];               // shared by dynamic-smem kernels

// ---------------------------------------------------------------------------
__global__ void init_kernel() {
    int i = blockIdx.x * blockDim.x + threadIdx.x;
    if (i < H_*B_) { g_hT[0][i] = 0.f; g_hT[1][i] = 0.f; }
}

__device__ __forceinline__ void ffma2(unsigned long long& acc,
                                      unsigned long long a, unsigned long long b) {
    asm("fma.rn.f32x2 %0, %1, %2, %0;" : "+l"(acc) : "l"(a), "l"(b));
}
__device__ __forceinline__ float2 u2f(unsigned long long u) {
    union { unsigned long long u; float2 f; } v; v.u = u; return v.f;
}
__device__ __forceinline__ float sigm(float v) { return 1.f / (1.f + expf(-v)); }

__device__ __forceinline__ uint32_t smem_u32(const void* p) {
    return (uint32_t)__cvta_generic_to_shared(p);
}
__device__ __forceinline__ void ldsm_x4(uint32_t* r, uint32_t addr) {
    asm volatile("ldmatrix.sync.aligned.m8n8.x4.shared.b16 {%0,%1,%2,%3}, [%4];"
        : "=r"(r[0]), "=r"(r[1]), "=r"(r[2]), "=r"(r[3]) : "r"(addr));
}
__device__ __forceinline__ void ldsm_x4_t(uint32_t* r, uint32_t addr) {
    asm volatile("ldmatrix.sync.aligned.m8n8.x4.trans.shared.b16 {%0,%1,%2,%3}, [%4];"
        : "=r"(r[0]), "=r"(r[1]), "=r"(r[2]), "=r"(r[3]) : "r"(addr));
}
__device__ __forceinline__ void mma_bf16(float* d, const uint32_t* a,
                                         uint32_t b0, uint32_t b1) {
    asm volatile("mma.sync.aligned.m16n8k16.row.col.f32.bf16.bf16.f32 "
        "{%0,%1,%2,%3}, {%4,%5,%6,%7}, {%8,%9}, {%0,%1,%2,%3};"
        : "+f"(d[0]), "+f"(d[1]), "+f"(d[2]), "+f"(d[3])
        : "r"(a[0]), "r"(a[1]), "r"(a[2]), "r"(a[3]), "r"(b0), "r"(b1));
}
__device__ __forceinline__ void cvt2(float x, float y, uint32_t& h, uint32_t& l) {
    __nv_bfloat162 hv, lv;
    hv.x = __float2bfloat16(x);
    hv.y = __float2bfloat16(y);
    lv.x = __float2bfloat16(x - __bfloat162float(hv.x));
    lv.y = __float2bfloat16(y - __bfloat162float(hv.y));
    h = *reinterpret_cast<uint32_t*>(&hv);
    l = *reinterpret_cast<uint32_t*>(&lv);
}

// ---------------------------------------------------------------------------
// Phase 1 (tensor cores), software-pipelined:
//   regs <- gmem loads for ko+1 issued BEFORE ko's MMA work; cvt+STS at the
//   top of the next iteration. Hides L2/DRAM latency under HMMA compute.
// ---------------------------------------------------------------------------
__global__ __launch_bounds__(256, 1) void pre_gemm_mma(
    const int*   __restrict__ x,
    const float* __restrict__ emb,
    const float* __restrict__ W,     // [K_, 512] for this gate
    int gate)
{
    __nv_bfloat16* As_hi = (__nv_bfloat16*)dynsm;          // [128][ASTR]
    __nv_bfloat16* As_lo = As_hi + 128*ASTR;
    __nv_bfloat16* Bs_hi = As_lo + 128*ASTR;               // [32][BSTR]
    __nv_bfloat16* Bs_lo = Bs_hi + 32*BSTR;
    int*           sx    = (int*)(Bs_lo + 32*BSTR);        // [128][16]

    const int tid = threadIdx.x;
    const int m0  = blockIdx.y * 128;
    const int nb  = blockIdx.x * 128;

    for (int lin = tid; lin < 2048; lin += 256) {
        int mm = lin >> 4, p = lin & 15;
        int m = m0 + mm;
        sx[mm*16 + p] = x[(m & 63)*4096 + p*256 + (m >> 6)];
    }

    const int w = tid >> 5, lane = tid & 31;
    const int warp_m = (w & 1) * 64;
    const int warp_n = (w >> 1) * 32;

    const int a_row  = w*16 + (lane & 15);
    const int a_half = lane >> 4;
    const int b_row  = (w & 3)*8 + (lane >> 2);
    const int b_wb   = (w >> 2)*32 + (lane & 3);

    const int am_off = lane & 15;
    const int ak_off = (lane >> 4) * 8;
    const int bk_off = ((lane >> 3) & 1)*8 + (lane & 7);
    const int bn_off = ((lane >> 4) & 1)*8;

    float acc[4][4][4];
    #pragma unroll
    for (int mi = 0; mi < 4; mi++)
        #pragma unroll
        for (int nt = 0; nt < 4; nt++)
            #pragma unroll
            for (int e = 0; e < 4; e++) acc[mi][nt][e] = 0.f;

    __syncthreads();   // sx ready

    float4 ra[4];
    float2 rb[8];

    // prologue: load ko = 0
    {
        int p = 0, i0 = 0;
        int idx = sx[a_row*16 + p];
        const float4* src = (const float4*)(emb + (size_t)idx * I_ + i0 + a_half*16);
        #pragma unroll
        for (int q = 0; q < 4; q++)
            ra[q] = idx ? __ldg(src + q) : make_float4(0.f, 0.f, 0.f, 0.f);
        const float* wr = W + (size_t)b_row * H_ + nb;
        #pragma unroll
        for (int j = 0; j < 8; j++)
            rb[j] = *(const float2*)(wr + 2*(b_wb + 4*j));
    }

    for (int ko = 0; ko < 128; ko++) {
        // ---- cvt + store current regs to smem
        {
            __nv_bfloat16* dh = As_hi + a_row*ASTR + a_half*16;
            __nv_bfloat16* dl = As_lo + a_row*ASTR + a_half*16;
            #pragma unroll
            for (int q = 0; q < 4; q++) {
                uint32_t h0, l0, h1, l1;
                cvt2(ra[q].x, ra[q].y, h0, l0);
                cvt2(ra[q].z, ra[q].w, h1, l1);
                *(uint32_t*)(dh + q*4)     = h0;
                *(uint32_t*)(dh + q*4 + 2) = h1;
                *(uint32_t*)(dl + q*4)     = l0;
                *(uint32_t*)(dl + q*4 + 2) = l1;
            }
            __nv_bfloat16* bdh = Bs_hi + b_row*BSTR;
            __nv_bfloat16* bdl = Bs_lo + b_row*BSTR;
            #pragma unroll
            for (int j = 0; j < 8; j++) {
                int cw = b_wb + 4*j;
                uint32_t h, l;
                cvt2(rb[j].x, rb[j].y, h, l);
                *(uint32_t*)(bdh + 2*cw) = h;
                *(uint32_t*)(bdl + 2*cw) = l;
            }
        }
        __syncthreads();

        // ---- issue ko+1 global loads EARLY (consumed next iteration)
        if (ko + 1 < 128) {
            int kn = ko + 1;
            int p = kn >> 3, i0 = (kn & 7) << 5;
            int idx = sx[a_row*16 + p];
            const float4* src = (const float4*)(emb + (size_t)idx * I_ + i0 + a_half*16);
            #pragma unroll
            for (int q = 0; q < 4; q++)
                ra[q] = idx ? __ldg(src + q) : make_float4(0.f, 0.f, 0.f, 0.f);
            const float* wr = W + (size_t)(kn*32 + b_row) * H_ + nb;
            #pragma unroll
            for (int j = 0; j < 8; j++)
                rb[j] = *(const float2*)(wr + 2*(b_wb + 4*j));
        }

        // ---- MMA work for ko (overlaps in-flight loads)
        #pragma unroll
        for (int ks = 0; ks < 2; ks++) {
            uint32_t ah[4][4], bh[8];
            #pragma unroll
            for (int mi = 0; mi < 4; mi++)
                ldsm_x4(ah[mi], smem_u32(As_hi + (warp_m + mi*16 + am_off)*ASTR
                                               + ks*16 + ak_off));
            #pragma unroll
            for (int j2 = 0; j2 < 2; j2++)
                ldsm_x4_t(&bh[j2*4], smem_u32(Bs_hi + (ks*16 + bk_off)*BSTR
                                                    + warp_n + j2*16 + bn_off));
            #pragma unroll
            for (int mi = 0; mi < 4; mi++)
                #pragma unroll
                for (int nt = 0; nt < 4; nt++)
                    mma_bf16(acc[mi][nt], ah[mi], bh[nt*2], bh[nt*2+1]);

            uint32_t bl[8];
            #pragma unroll
            for (int j2 = 0; j2 < 2; j2++)
                ldsm_x4_t(&bl[j2*4], smem_u32(Bs_lo + (ks*16 + bk_off)*BSTR
                                                    + warp_n + j2*16 + bn_off));
            #pragma unroll
            for (int mi = 0; mi < 4; mi++)
                #pragma unroll
                for (int nt = 0; nt < 4; nt++)
                    mma_bf16(acc[mi][nt], ah[mi], bl[nt*2], bl[nt*2+1]);

            uint32_t al[4];
            #pragma unroll
            for (int mi = 0; mi < 4; mi++) {
                ldsm_x4(al, smem_u32(As_lo + (warp_m + mi*16 + am_off)*ASTR
                                           + ks*16 + ak_off));
                #pragma unroll
                for (int nt = 0; nt < 4; nt++)
                    mma_bf16(acc[mi][nt], al, bh[nt*2], bh[nt*2+1]);
            }
        }
        __syncthreads();
    }

    const int er = lane >> 2, ec = (lane & 3)*2;
    #pragma unroll
    for (int mi = 0; mi < 4; mi++)
        #pragma unroll
        for (int nt = 0; nt < 4; nt++) {
            int row = m0 + warp_m + mi*16 + er;
            int col = gate*H_ + nb + warp_n + nt*8 + ec;
            float2 v0 = make_float2(acc[mi][nt][0], acc[mi][nt][1]);
            float2 v1 = make_float2(acc[mi][nt][2], acc[mi][nt][3]);
            __stcs((float2*)&g_pre[(size_t)row * NCOL + col], v0);
            __stcs((float2*)&g_pre[(size_t)(row + 8) * NCOL + col], v1);
        }
}

// ---------------------------------------------------------------------------
// grid barrier (128 blocks co-resident)
// ---------------------------------------------------------------------------
__device__ __forceinline__ void grid_barrier() {
    __threadfence();
    __syncthreads();
    if (threadIdx.x == 0) {
        unsigned gen = *(volatile unsigned*)&g_bar_gen;
        if (atomicAdd(&g_bar_cnt, 1u) == NBLK - 1) {
            atomicExch(&g_bar_cnt, 0u);
            atomicAdd(&g_bar_gen, 1u);
        } else {
            unsigned cur;
            do {
                __nanosleep(64);
                asm volatile("ld.global.acquire.gpu.u32 %0, [%1];"
                             : "=r"(cur) : "l"(&g_bar_gen));
            } while (cur == gen);
        }
        __threadfence();
    }
    __syncthreads();
}

// ---------------------------------------------------------------------------
// Phase 2: persistent recurrence (unchanged from round 7)
// ---------------------------------------------------------------------------
__global__ __launch_bounds__(512, 1) void lstm_persist_kernel(
    const float* __restrict__ Wfh, const float* __restrict__ Wih,
    const float* __restrict__ Wgh, const float* __restrict__ Woh,
    const float* __restrict__ bf,  const float* __restrict__ bi,
    const float* __restrict__ bg,  const float* __restrict__ bo)
{
    unsigned long long* ws2 = (unsigned long long*)dynsm;       // [512][16] dup f32x2
    float4* hbuf = (float4*)(dynsm + 65536);                    // 4 x [2048] float4
    float*  sg   = (float*)(dynsm + 65536 + 131072);            // 2 x [64][17]

    const int tid  = threadIdx.x;
    const int kh   = tid >> 8;
    const int stid = tid & 255;
    const int tx   = stid & 15;
    const int ty   = stid >> 4;
    const int hc0  = blockIdx.x * 4;

    for (int idx = tid; idx < 512*16; idx += 512) {
        int k = idx >> 4, c = idx & 15;
        int g = c >> 2;
        const float* Wp = (g == 0) ? Wfh : (g == 1) ? Wih : (g == 2) ? Wgh : Woh;
        float wv = Wp[k*H_ + hc0 + (c & 3)];
        float2 w2 = make_float2(wv, wv);
        ws2[idx] = *reinterpret_cast<unsigned long long*>(&w2);
    }

    const int pb  = stid >> 2, pj = stid & 3;
    const int phc = hc0 + pj;
    const float bfv = bf[phc], biv = bi[phc], bgv = bg[phc], bov = bo[phc];
    const float* preb = g_pre + (size_t)pb * NCOL + phc;
    float creg = 0.f;

    __syncthreads();

    for (int t = 0; t < T_; t++) {
        const int cur = t & 1, nxt = cur ^ 1;

        float pf, pi, pg, po;
        if (kh == 0) {
            const float* pp = preb + (size_t)t * 64 * NCOL;
            pf = __ldcs(pp);
            pi = __ldcs(pp + 512);
            pg = __ldcs(pp + 1024);
            po = __ldcs(pp + 1536);
        }

        const float4* h4 = (const float4*)g_hT[cur];
        unsigned long long acc0 = 0ULL, acc1 = 0ULL, acc2 = 0ULL, acc3 = 0ULL;

        float4 r[8];
        {
            const float4* src = h4 + (kh*2) * 2048 + stid;
            #pragma unroll
            for (int q = 0; q < 8; q++) r[q] = __ldcg(src + q*256);
        }

        #pragma unroll
        for (int cc = 0; cc < 2; cc++) {
            const int c = kh*2 + cc;
            float4* buf = hbuf + (size_t)(kh*2 + cc) * 2048;
            #pragma unroll
            for (int q = 0; q < 8; q++) buf[stid + q*256] = r[q];
            __syncthreads();
            if (cc == 0) {
                const float4* src = h4 + (kh*2 + 1) * 2048 + stid;
                #pragma unroll
                for (int q = 0; q < 8; q++) r[q] = __ldcg(src + q*256);
            }
            const ulonglong2* hb = (const ulonglong2*)buf;
            const unsigned long long* wsb = ws2 + (size_t)c * 128 * 16;
            #pragma unroll 8
            for (int kk = 0; kk < 128; kk++) {
                ulonglong2 a = hb[kk*16 + ty];
                unsigned long long wv = wsb[kk*16 + tx];
                if (kk & 1) { ffma2(acc2, a.x, wv); ffma2(acc3, a.y, wv); }
                else        { ffma2(acc0, a.x, wv); ffma2(acc1, a.y, wv); }
            }
            __syncthreads();
        }

        float2 e0 = u2f(acc0), o0 = u2f(acc2), e1 = u2f(acc1), o1 = u2f(acc3);
        float* sgh = sg + kh * (64*17);
        sgh[(4*ty + 0)*17 + tx] = e0.x + o0.x;
        sgh[(4*ty + 1)*17 + tx] = e0.y + o0.y;
        sgh[(4*ty + 2)*17 + tx] = e1.x + o1.x;
        sgh[(4*ty + 3)*17 + tx] = e1.y + o1.y;
        __syncthreads();

        if (kh == 0) {
            float f  = sigm(pf + bfv + sg[pb*17 + pj]        + sg[64*17 + pb*17 + pj]);
            float ii = sigm(pi + biv + sg[pb*17 + 4 + pj]    + sg[64*17 + pb*17 + 4 + pj]);
            float gg = tanhf(pg + bgv + sg[pb*17 + 8 + pj]   + sg[64*17 + pb*17 + 8 + pj]);
            float oo = sigm(po + bov + sg[pb*17 + 12 + pj]   + sg[64*17 + pb*17 + 12 + pj]);
            float cn = f * creg + ii * gg;
            float hn = oo * tanhf(cn);
            creg = cn;
            __stcg(&g_hT[nxt][phc*64 + pb], hn);
            if (t == T_ - 1) g_cfin[pb*H_ + phc] = cn;
        }

        if (t < T_ - 1) grid_barrier();
    }
}

// ---------------------------------------------------------------------------
// Phase 3: out = h_T @ W_lin + b_lin; emit (out, h_t, c_t)
// ---------------------------------------------------------------------------
__global__ void final_kernel(const float* __restrict__ Wlin,
                             const float* __restrict__ blin,
                             float* __restrict__ out)
{
    int b = blockIdx.x;
    int tid = threadIdx.x;  // 512
    __shared__ float sh[H_];
    float hv = g_hT[0][tid*64 + b];
    sh[tid] = hv;
    out[B_*O_ + b*H_ + tid]          = hv;
    out[B_*O_ + B_*H_ + b*H_ + tid]  = g_cfin[b*H_ + tid];
    __syncthreads();
    if (tid < O_) {
        float s = blin[tid];
        for (int k = 0; k < H_; k++) s += sh[k] * Wlin[k*O_ + tid];
        out[b*O_ + tid] = s;
    }
}

// ---------------------------------------------------------------------------
extern "C" void kernel_launch(void* const* d_in, const int* in_sizes, int n_in,
                              void* d_out, int out_size)
{
    const int*   x    = (const int*)  d_in[0];
    const float* emb  = (const float*)d_in[1];
    const float* Wfx  = (const float*)d_in[2];
    const float* Wfh  = (const float*)d_in[3];
    const float* bf   = (const float*)d_in[4];
    const float* Wix  = (const float*)d_in[5];
    const float* Wih  = (const float*)d_in[6];
    const float* bi   = (const float*)d_in[7];
    const float* Wgx  = (const float*)d_in[8];
    const float* Wgh  = (const float*)d_in[9];
    const float* bg   = (const float*)d_in[10];
    const float* Wox  = (const float*)d_in[11];
    const float* Woh  = (const float*)d_in[12];
    const float* bo   = (const float*)d_in[13];
    const float* Wlin = (const float*)d_in[14];
    const float* blin = (const float*)d_in[15];
    float* out = (float*)d_out;

    const int mma_dyn = (128*ASTR*2 + 32*BSTR*2) * 2 + 128*16*4;   // 54272
    cudaFuncSetAttribute(pre_gemm_mma,
                         cudaFuncAttributeMaxDynamicSharedMemorySize, mma_dyn);

    init_kernel<<<(H_*B_ + 255)/256, 256>>>();                     // launch 1

    dim3 gfull(4, 128);
    pre_gemm_mma<<<gfull, 256, mma_dyn>>>(x, emb, Wfx, 0);         // 2
    pre_gemm_mma<<<gfull, 256, mma_dyn>>>(x, emb, Wix, 1);         // 3
    pre_gemm_mma<<<gfull, 256, mma_dyn>>>(x, emb, Wgx, 2);         // 4
    pre_gemm_mma<<<gfull, 256, mma_dyn>>>(x, emb, Wox, 3);         // 5

    cudaFuncSetAttribute(lstm_persist_kernel,
                         cudaFuncAttributeMaxDynamicSharedMemorySize, 205312);
    lstm_persist_kernel<<<NBLK, 512, 205312>>>(Wfh, Wih, Wgh, Woh, // 6 <- ncu
                                               bf, bi, bg, bo);

    final_kernel<<<B_, H_>>>(Wlin, blin, out);                     // 7
}

// round 11
// speedup vs baseline: 4.0236x; 1.0770x over previous
#include <cuda_runtime.h>
#include <cuda_bf16.h>
#include <cstdint>
#include <stdint.h>
#include <math.h>

#define B_   64
#define P_   16
#define T_   256
#define I_   256
#define H_   512
#define O_   5
#define V_   50000
#define NCOL 2048            // 4 gates * H
#define M_   (T_*B_)         // 16384 rows (t-major, b-minor)
#define K_   (P_*I_)         // 4096
#define NBLK 128             // persistent blocks for recurrence

#define ASTR 56              // A smem row stride (bf16 elems)
#define BSTR 136             // B smem row stride

// Scratch (static __device__ — no allocations allowed)
__device__ float g_pre[(size_t)M_ * NCOL];    // 134 MB gate pre-activations
__device__ float g_hT[2][H_ * B_];            // transposed hidden state [hcol][b]
__device__ float g_cfin[B_ * H_];             // final cell state
__device__ unsigned g_bar_gen;
__device__ unsigned g_bar_cnt;

// pre-split bf16 tables (filled once per run by prep kernels)
__device__ __nv_bfloat16 g_emb_hi[(size_t)V_ * I_];   // 25.6 MB
__device__ __nv_bfloat16 g_emb_lo[(size_t)V_ * I_];
__device__ __nv_bfloat16 g_W_hi[4][(size_t)K_ * H_];  // 16.8 MB
__device__ __nv_bfloat16 g_W_lo[4][(size_t)K_ * H_];

extern __shared__ char dynsm[];               // shared by dynamic-smem kernels

// ---------------------------------------------------------------------------
__device__ __forceinline__ void ffma2(unsigned long long& acc,
                                      unsigned long long a, unsigned long long b) {
    asm("fma.rn.f32x2 %0, %1, %2, %0;" : "+l"(acc) : "l"(a), "l"(b));
}
__device__ __forceinline__ float2 u2f(unsigned long long u) {
    union { unsigned long long u; float2 f; } v; v.u = u; return v.f;
}
__device__ __forceinline__ float sigm(float v) { return 1.f / (1.f + expf(-v)); }

__device__ __forceinline__ uint32_t smem_u32(const void* p) {
    return (uint32_t)__cvta_generic_to_shared(p);
}
__device__ __forceinline__ void ldsm_x4(uint32_t* r, uint32_t addr) {
    asm volatile("ldmatrix.sync.aligned.m8n8.x4.shared.b16 {%0,%1,%2,%3}, [%4];"
        : "=r"(r[0]), "=r"(r[1]), "=r"(r[2]), "=r"(r[3]) : "r"(addr));
}
__device__ __forceinline__ void ldsm_x4_t(uint32_t* r, uint32_t addr) {
    asm volatile("ldmatrix.sync.aligned.m8n8.x4.trans.shared.b16 {%0,%1,%2,%3}, [%4];"
        : "=r"(r[0]), "=r"(r[1]), "=r"(r[2]), "=r"(r[3]) : "r"(addr));
}
__device__ __forceinline__ void mma_bf16(float* d, const uint32_t* a,
                                         uint32_t b0, uint32_t b1) {
    asm volatile("mma.sync.aligned.m16n8k16.row.col.f32.bf16.bf16.f32 "
        "{%0,%1,%2,%3}, {%4,%5,%6,%7}, {%8,%9}, {%0,%1,%2,%3};"
        : "+f"(d[0]), "+f"(d[1]), "+f"(d[2]), "+f"(d[3])
        : "r"(a[0]), "r"(a[1]), "r"(a[2]), "r"(a[3]), "r"(b0), "r"(b1));
}
__device__ __forceinline__ void cvt2(float x, float y, uint32_t& h, uint32_t& l) {
    __nv_bfloat162 hv, lv;
    hv.x = __float2bfloat16(x);
    hv.y = __float2bfloat16(y);
    lv.x = __float2bfloat16(x - __bfloat162float(hv.x));
    lv.y = __float2bfloat16(y - __bfloat162float(hv.y));
    h = *reinterpret_cast<uint32_t*>(&hv);
    l = *reinterpret_cast<uint32_t*>(&lv);
}

// ---------------------------------------------------------------------------
// Prep: split fp32 -> bf16 hi/lo tables (pure bandwidth, ~25us total)
// ---------------------------------------------------------------------------
__global__ void conv_emb_kernel(const float* __restrict__ emb) {
    int i = blockIdx.x * blockDim.x + threadIdx.x;     // over V_*I_/4 float4s
    float4 v = __ldg((const float4*)emb + i);
    uint32_t h0, l0, h1, l1;
    cvt2(v.x, v.y, h0, l0);
    cvt2(v.z, v.w, h1, l1);
    ((uint2*)g_emb_hi)[i] = make_uint2(h0, h1);
    ((uint2*)g_emb_lo)[i] = make_uint2(l0, l1);
}
__global__ void conv_w_kernel(const float* __restrict__ Wf, const float* __restrict__ Wi,
                              const float* __restrict__ Wg, const float* __restrict__ Wo) {
    int g = blockIdx.y;
    const float* W = (g == 0) ? Wf : (g == 1) ? Wi : (g == 2) ? Wg : Wo;
    int i = blockIdx.x * blockDim.x + threadIdx.x;     // over K_*H_/4 float4s
    float4 v = __ldg((const float4*)W + i);
    uint32_t h0, l0, h1, l1;
    cvt2(v.x, v.y, h0, l0);
    cvt2(v.z, v.w, h1, l1);
    ((uint2*)g_W_hi[g])[i] = make_uint2(h0, h1);
    ((uint2*)g_W_lo[g])[i] = make_uint2(l0, l1);
}

__global__ void init_kernel() {
    int i = blockIdx.x * blockDim.x + threadIdx.x;
    if (i < H_*B_) { g_hT[0][i] = 0.f; g_hT[1][i] = 0.f; }
}

// ---------------------------------------------------------------------------
// Phase 1 (tensor cores), software-pipelined, NO in-loop conversion:
// loads pre-split bf16 hi/lo directly; inner loop = LDG.128 -> STS.128 ->
// ldmatrix -> MMA (3-product split, fp32 accum).
// ---------------------------------------------------------------------------
__global__ __launch_bounds__(256, 1) void pre_gemm_mma(
    const int* __restrict__ x, int gate)
{
    __nv_bfloat16* As_hi = (__nv_bfloat16*)dynsm;          // [128][ASTR]
    __nv_bfloat16* As_lo = As_hi + 128*ASTR;
    __nv_bfloat16* Bs_hi = As_lo + 128*ASTR;               // [32][BSTR]
    __nv_bfloat16* Bs_lo = Bs_hi + 32*BSTR;
    int*           sx    = (int*)(Bs_lo + 32*BSTR);        // [128][16]

    const int tid = threadIdx.x;
    const int m0  = blockIdx.y * 128;
    const int nb  = blockIdx.x * 128;

    const __nv_bfloat16* Wh = g_W_hi[gate];
    const __nv_bfloat16* Wl = g_W_lo[gate];

    for (int lin = tid; lin < 2048; lin += 256) {
        int mm = lin >> 4, p = lin & 15;
        int m = m0 + mm;
        sx[mm*16 + p] = x[(m & 63)*4096 + p*256 + (m >> 6)];
    }

    const int w = tid >> 5, lane = tid & 31;
    const int warp_m = (w & 1) * 64;
    const int warp_n = (w >> 1) * 32;

    // A fill: row = w*16 + (lane&15), 16 k-elems at half (lane>>4)*16
    const int a_row  = w*16 + (lane & 15);
    const int a_half = lane >> 4;
    // B fill: row = tid>>3 (0..31), 16 cols at (tid&7)*16
    const int b_row2 = tid >> 3;
    const int b_seg  = tid & 7;

    // ldmatrix lane offsets
    const int am_off = lane & 15;
    const int ak_off = (lane >> 4) * 8;
    const int bk_off = ((lane >> 3) & 1)*8 + (lane & 7);
    const int bn_off = ((lane >> 4) & 1)*8;

    float acc[4][4][4];
    #pragma unroll
    for (int mi = 0; mi < 4; mi++)
        #pragma unroll
        for (int nt = 0; nt < 4; nt++)
            #pragma unroll
            for (int e = 0; e < 4; e++) acc[mi][nt][e] = 0.f;

    __syncthreads();   // sx ready

    uint4 rah[2], ral[2], rbh[2], rbl[2];

    // prologue: load ko = 0
    {
        int idx = sx[a_row*16 + 0];
        const uint4* sh = (const uint4*)(g_emb_hi + (size_t)idx * I_ + a_half*16);
        const uint4* sl = (const uint4*)(g_emb_lo + (size_t)idx * I_ + a_half*16);
        if (idx) {
            rah[0] = __ldg(sh); rah[1] = __ldg(sh + 1);
            ral[0] = __ldg(sl); ral[1] = __ldg(sl + 1);
        } else {
            rah[0] = rah[1] = ral[0] = ral[1] = make_uint4(0u, 0u, 0u, 0u);
        }
        const uint4* wh = (const uint4*)(Wh + (size_t)b_row2 * H_ + nb + b_seg*16);
        const uint4* wl = (const uint4*)(Wl + (size_t)b_row2 * H_ + nb + b_seg*16);
        rbh[0] = __ldg(wh); rbh[1] = __ldg(wh + 1);
        rbl[0] = __ldg(wl); rbl[1] = __ldg(wl + 1);
    }

    for (int ko = 0; ko < 128; ko++) {
        // ---- store current regs to smem (STS.128 only, no conversion)
        {
            __nv_bfloat16* dah = As_hi + a_row*ASTR + a_half*16;
            __nv_bfloat16* dal = As_lo + a_row*ASTR + a_half*16;
            *(uint4*)(dah)     = rah[0];
            *(uint4*)(dah + 8) = rah[1];
            *(uint4*)(dal)     = ral[0];
            *(uint4*)(dal + 8) = ral[1];
            __nv_bfloat16* dbh = Bs_hi + b_row2*BSTR + b_seg*16;
            __nv_bfloat16* dbl = Bs_lo + b_row2*BSTR + b_seg*16;
            *(uint4*)(dbh)     = rbh[0];
            *(uint4*)(dbh + 8) = rbh[1];
            *(uint4*)(dbl)     = rbl[0];
            *(uint4*)(dbl + 8) = rbl[1];
        }
        __syncthreads();

        // ---- issue ko+1 global loads EARLY (consumed next iteration)
        if (ko + 1 < 128) {
            int kn = ko + 1;
            int p = kn >> 3, i0 = (kn & 7) << 5;
            int idx = sx[a_row*16 + p];
            const uint4* sh = (const uint4*)(g_emb_hi + (size_t)idx * I_ + i0 + a_half*16);
            const uint4* sl = (const uint4*)(g_emb_lo + (size_t)idx * I_ + i0 + a_half*16);
            if (idx) {
                rah[0] = __ldg(sh); rah[1] = __ldg(sh + 1);
                ral[0] = __ldg(sl); ral[1] = __ldg(sl + 1);
            } else {
                rah[0] = rah[1] = ral[0] = ral[1] = make_uint4(0u, 0u, 0u, 0u);
            }
            const uint4* wh = (const uint4*)(Wh + (size_t)(kn*32 + b_row2) * H_ + nb + b_seg*16);
            const uint4* wl = (const uint4*)(Wl + (size_t)(kn*32 + b_row2) * H_ + nb + b_seg*16);
            rbh[0] = __ldg(wh); rbh[1] = __ldg(wh + 1);
            rbl[0] = __ldg(wl); rbl[1] = __ldg(wl + 1);
        }

        // ---- MMA work for ko (overlaps in-flight loads)
        #pragma unroll
        for (int ks = 0; ks < 2; ks++) {
            uint32_t ah[4][4], bh[8];
            #pragma unroll
            for (int mi = 0; mi < 4; mi++)
                ldsm_x4(ah[mi], smem_u32(As_hi + (warp_m + mi*16 + am_off)*ASTR
                                               + ks*16 + ak_off));
            #pragma unroll
            for (int j2 = 0; j2 < 2; j2++)
                ldsm_x4_t(&bh[j2*4], smem_u32(Bs_hi + (ks*16 + bk_off)*BSTR
                                                    + warp_n + j2*16 + bn_off));
            #pragma unroll
            for (int mi = 0; mi < 4; mi++)
                #pragma unroll
                for (int nt = 0; nt < 4; nt++)
                    mma_bf16(acc[mi][nt], ah[mi], bh[nt*2], bh[nt*2+1]);

            uint32_t bl[8];
            #pragma unroll
            for (int j2 = 0; j2 < 2; j2++)
                ldsm_x4_t(&bl[j2*4], smem_u32(Bs_lo + (ks*16 + bk_off)*BSTR
                                                    + warp_n + j2*16 + bn_off));
            #pragma unroll
            for (int mi = 0; mi < 4; mi++)
                #pragma unroll
                for (int nt = 0; nt < 4; nt++)
                    mma_bf16(acc[mi][nt], ah[mi], bl[nt*2], bl[nt*2+1]);

            uint32_t al[4];
            #pragma unroll
            for (int mi = 0; mi < 4; mi++) {
                ldsm_x4(al, smem_u32(As_lo + (warp_m + mi*16 + am_off)*ASTR
                                           + ks*16 + ak_off));
                #pragma unroll
                for (int nt = 0; nt < 4; nt++)
                    mma_bf16(acc[mi][nt], al, bh[nt*2], bh[nt*2+1]);
            }
        }
        __syncthreads();
    }

    const int er = lane >> 2, ec = (lane & 3)*2;
    #pragma unroll
    for (int mi = 0; mi < 4; mi++)
        #pragma unroll
        for (int nt = 0; nt < 4; nt++) {
            int row = m0 + warp_m + mi*16 + er;
            int col = gate*H_ + nb + warp_n + nt*8 + ec;
            float2 v0 = make_float2(acc[mi][nt][0], acc[mi][nt][1]);
            float2 v1 = make_float2(acc[mi][nt][2], acc[mi][nt][3]);
            __stcs((float2*)&g_pre[(size_t)row * NCOL + col], v0);
            __stcs((float2*)&g_pre[(size_t)(row + 8) * NCOL + col], v1);
        }
}

// ---------------------------------------------------------------------------
// grid barrier (128 blocks co-resident)
// ---------------------------------------------------------------------------
__device__ __forceinline__ void grid_barrier() {
    __threadfence();
    __syncthreads();
    if (threadIdx.x == 0) {
        unsigned gen = *(volatile unsigned*)&g_bar_gen;
        if (atomicAdd(&g_bar_cnt, 1u) == NBLK - 1) {
            atomicExch(&g_bar_cnt, 0u);
            atomicAdd(&g_bar_gen, 1u);
        } else {
            unsigned cur;
            do {
                __nanosleep(64);
                asm volatile("ld.global.acquire.gpu.u32 %0, [%1];"
                             : "=r"(cur) : "l"(&g_bar_gen));
            } while (cur == gen);
        }
        __threadfence();
    }
    __syncthreads();
}

// ---------------------------------------------------------------------------
// Phase 2: persistent recurrence (unchanged from round 7)
// ---------------------------------------------------------------------------
__global__ __launch_bounds__(512, 1) void lstm_persist_kernel(
    const float* __restrict__ Wfh, const float* __restrict__ Wih,
    const float* __restrict__ Wgh, const float* __restrict__ Woh,
    const float* __restrict__ bf,  const float* __restrict__ bi,
    const float* __restrict__ bg,  const float* __restrict__ bo)
{
    unsigned long long* ws2 = (unsigned long long*)dynsm;       // [512][16] dup f32x2
    float4* hbuf = (float4*)(dynsm + 65536);                    // 4 x [2048] float4
    float*  sg   = (float*)(dynsm + 65536 + 131072);            // 2 x [64][17]

    const int tid  = threadIdx.x;
    const int kh   = tid >> 8;
    const int stid = tid & 255;
    const int tx   = stid & 15;
    const int ty   = stid >> 4;
    const int hc0  = blockIdx.x * 4;

    for (int idx = tid; idx < 512*16; idx += 512) {
        int k = idx >> 4, c = idx & 15;
        int g = c >> 2;
        const float* Wp = (g == 0) ? Wfh : (g == 1) ? Wih : (g == 2) ? Wgh : Woh;
        float wv = Wp[k*H_ + hc0 + (c & 3)];
        float2 w2 = make_float2(wv, wv);
        ws2[idx] = *reinterpret_cast<unsigned long long*>(&w2);
    }

    const int pb  = stid >> 2, pj = stid & 3;
    const int phc = hc0 + pj;
    const float bfv = bf[phc], biv = bi[phc], bgv = bg[phc], bov = bo[phc];
    const float* preb = g_pre + (size_t)pb * NCOL + phc;
    float creg = 0.f;

    __syncthreads();

    for (int t = 0; t < T_; t++) {
        const int cur = t & 1, nxt = cur ^ 1;

        float pf, pi, pg, po;
        if (kh == 0) {
            const float* pp = preb + (size_t)t * 64 * NCOL;
            pf = __ldcs(pp);
            pi = __ldcs(pp + 512);
            pg = __ldcs(pp + 1024);
            po = __ldcs(pp + 1536);
        }

        const float4* h4 = (const float4*)g_hT[cur];
        unsigned long long acc0 = 0ULL, acc1 = 0ULL, acc2 = 0ULL, acc3 = 0ULL;

        float4 r[8];
        {
            const float4* src = h4 + (kh*2) * 2048 + stid;
            #pragma unroll
            for (int q = 0; q < 8; q++) r[q] = __ldcg(src + q*256);
        }

        #pragma unroll
        for (int cc = 0; cc < 2; cc++) {
            const int c = kh*2 + cc;
            float4* buf = hbuf + (size_t)(kh*2 + cc) * 2048;
            #pragma unroll
            for (int q = 0; q < 8; q++) buf[stid + q*256] = r[q];
            __syncthreads();
            if (cc == 0) {
                const float4* src = h4 + (kh*2 + 1) * 2048 + stid;
                #pragma unroll
                for (int q = 0; q < 8; q++) r[q] = __ldcg(src + q*256);
            }
            const ulonglong2* hb = (const ulonglong2*)buf;
            const unsigned long long* wsb = ws2 + (size_t)c * 128 * 16;
            #pragma unroll 8
            for (int kk = 0; kk < 128; kk++) {
                ulonglong2 a = hb[kk*16 + ty];
                unsigned long long wv = wsb[kk*16 + tx];
                if (kk & 1) { ffma2(acc2, a.x, wv); ffma2(acc3, a.y, wv); }
                else        { ffma2(acc0, a.x, wv); ffma2(acc1, a.y, wv); }
            }
            __syncthreads();
        }

        float2 e0 = u2f(acc0), o0 = u2f(acc2), e1 = u2f(acc1), o1 = u2f(acc3);
        float* sgh = sg + kh * (64*17);
        sgh[(4*ty + 0)*17 + tx] = e0.x + o0.x;
        sgh[(4*ty + 1)*17 + tx] = e0.y + o0.y;
        sgh[(4*ty + 2)*17 + tx] = e1.x + o1.x;
        sgh[(4*ty + 3)*17 + tx] = e1.y + o1.y;
        __syncthreads();

        if (kh == 0) {
            float f  = sigm(pf + bfv + sg[pb*17 + pj]        + sg[64*17 + pb*17 + pj]);
            float ii = sigm(pi + biv + sg[pb*17 + 4 + pj]    + sg[64*17 + pb*17 + 4 + pj]);
            float gg = tanhf(pg + bgv + sg[pb*17 + 8 + pj]   + sg[64*17 + pb*17 + 8 + pj]);
            float oo = sigm(po + bov + sg[pb*17 + 12 + pj]   + sg[64*17 + pb*17 + 12 + pj]);
            float cn = f * creg + ii * gg;
            float hn = oo * tanhf(cn);
            creg = cn;
            __stcg(&g_hT[nxt][phc*64 + pb], hn);
            if (t == T_ - 1) g_cfin[pb*H_ + phc] = cn;
        }

        if (t < T_ - 1) grid_barrier();
    }
}

// ---------------------------------------------------------------------------
// Phase 3: out = h_T @ W_lin + b_lin; emit (out, h_t, c_t)
// ---------------------------------------------------------------------------
__global__ void final_kernel(const float* __restrict__ Wlin,
                             const float* __restrict__ blin,
                             float* __restrict__ out)
{
    int b = blockIdx.x;
    int tid = threadIdx.x;  // 512
    __shared__ float sh[H_];
    float hv = g_hT[0][tid*64 + b];
    sh[tid] = hv;
    out[B_*O_ + b*H_ + tid]          = hv;
    out[B_*O_ + B_*H_ + b*H_ + tid]  = g_cfin[b*H_ + tid];
    __syncthreads();
    if (tid < O_) {
        float s = blin[tid];
        for (int k = 0; k < H_; k++) s += sh[k] * Wlin[k*O_ + tid];
        out[b*O_ + tid] = s;
    }
}

// ---------------------------------------------------------------------------
extern "C" void kernel_launch(void* const* d_in, const int* in_sizes, int n_in,
                              void* d_out, int out_size)
{
    const int*   x    = (const int*)  d_in[0];
    const float* emb  = (const float*)d_in[1];
    const float* Wfx  = (const float*)d_in[2];
    const float* Wfh  = (const float*)d_in[3];
    const float* bf   = (const float*)d_in[4];
    const float* Wix  = (const float*)d_in[5];
    const float* Wih  = (const float*)d_in[6];
    const float* bi   = (const float*)d_in[7];
    const float* Wgx  = (const float*)d_in[8];
    const float* Wgh  = (const float*)d_in[9];
    const float* bg   = (const float*)d_in[10];
    const float* Wox  = (const float*)d_in[11];
    const float* Woh  = (const float*)d_in[12];
    const float* bo   = (const float*)d_in[13];
    const float* Wlin = (const float*)d_in[14];
    const float* blin = (const float*)d_in[15];
    float* out = (float*)d_out;

    const int mma_dyn = (128*ASTR*2 + 32*BSTR*2) * 2 + 128*16*4;   // 54272
    cudaFuncSetAttribute(pre_gemm_mma,
                         cudaFuncAttributeMaxDynamicSharedMemorySize, mma_dyn);

    conv_emb_kernel<<<V_*I_/4/256, 256>>>(emb);                    // 1
    conv_w_kernel<<<dim3(K_*H_/4/256, 4), 256>>>(Wfx, Wix, Wgx, Wox); // 2

    dim3 gfull(4, 128);
    pre_gemm_mma<<<gfull, 256, mma_dyn>>>(x, 0);                   // 3
    pre_gemm_mma<<<gfull, 256, mma_dyn>>>(x, 1);                   // 4
    pre_gemm_mma<<<gfull, 256, mma_dyn>>>(x, 2);                   // 5
    pre_gemm_mma<<<gfull, 256, mma_dyn>>>(x, 3);                   // 6 <- ncu

    init_kernel<<<(H_*B_ + 255)/256, 256>>>();                     // 7

    cudaFuncSetAttribute(lstm_persist_kernel,
                         cudaFuncAttributeMaxDynamicSharedMemorySize, 205312);
    lstm_persist_kernel<<<NBLK, 512, 205312>>>(Wfh, Wih, Wgh, Woh, // 8
                                               bf, bi, bg, bo);

    final_kernel<<<B_, H_>>>(Wlin, blin, out);                     // 9
}

// round 14
// speedup vs baseline: 4.6821x; 1.1637x over previous
#include <cuda_runtime.h>
#include <cuda_bf16.h>
#include <cstdint>
#include <stdint.h>
#include <math.h>

#define B_   64
#define P_   16
#define T_   256
#define I_   256
#define H_   512
#define O_   5
#define V_   50000
#define NCOL 2048            // 4 gates * H
#define M_   (T_*B_)         // 16384 rows (t-major, b-minor)
#define K_   (P_*I_)         // 4096
#define NBLK 128             // persistent blocks for recurrence

#define ASTR 56              // A smem row stride (bf16 elems): 112B, 16B-aligned
#define BSTR 136             // B smem row stride: 272B, 16B-aligned
#define ABYTES (128*ASTR*2)  // 14336 per table
#define BBYTES (32*BSTR*2)   // 8704 per table
#define STAGE_BYTES (2*ABYTES + 2*BBYTES)   // 46080

// Scratch (static __device__ — no allocations allowed)
__device__ float g_pre[(size_t)M_ * NCOL];    // 134 MB gate pre-activations
__device__ float g_hT[2][H_ * B_];            // transposed hidden state [hcol][b]
__device__ float g_cfin[B_ * H_];             // final cell state
__device__ unsigned g_bar_gen;
__device__ unsigned g_bar_cnt;

// pre-split bf16 tables (filled once per run by prep kernels)
__device__ __nv_bfloat16 g_emb_hi[(size_t)V_ * I_];   // [V][I]
__device__ __nv_bfloat16 g_emb_lo[(size_t)V_ * I_];
__device__ __nv_bfloat16 g_W_hi[4][(size_t)K_ * H_];  // [gate][k][n]
__device__ __nv_bfloat16 g_W_lo[4][(size_t)K_ * H_];

extern __shared__ char dynsm[];               // shared by dynamic-smem kernels

// ---------------------------------------------------------------------------
__device__ __forceinline__ void ffma2(unsigned long long& acc,
                                      unsigned long long a, unsigned long long b) {
    asm("fma.rn.f32x2 %0, %1, %2, %0;" : "+l"(acc) : "l"(a), "l"(b));
}
__device__ __forceinline__ float2 u2f(unsigned long long u) {
    union { unsigned long long u; float2 f; } v; v.u = u; return v.f;
}
__device__ __forceinline__ float sigm(float v) { return 1.f / (1.f + expf(-v)); }

__device__ __forceinline__ uint32_t smem_u32(const void* p) {
    return (uint32_t)__cvta_generic_to_shared(p);
}
__device__ __forceinline__ void ldsm_x4(uint32_t* r, uint32_t addr) {
    asm volatile("ldmatrix.sync.aligned.m8n8.x4.shared.b16 {%0,%1,%2,%3}, [%4];"
        : "=r"(r[0]), "=r"(r[1]), "=r"(r[2]), "=r"(r[3]) : "r"(addr));
}
__device__ __forceinline__ void ldsm_x4_t(uint32_t* r, uint32_t addr) {
    asm volatile("ldmatrix.sync.aligned.m8n8.x4.trans.shared.b16 {%0,%1,%2,%3}, [%4];"
        : "=r"(r[0]), "=r"(r[1]), "=r"(r[2]), "=r"(r[3]) : "r"(addr));
}
__device__ __forceinline__ void mma_bf16(float* d, const uint32_t* a,
                                         uint32_t b0, uint32_t b1) {
    asm volatile("mma.sync.aligned.m16n8k16.row.col.f32.bf16.bf16.f32 "
        "{%0,%1,%2,%3}, {%4,%5,%6,%7}, {%8,%9}, {%0,%1,%2,%3};"
        : "+f"(d[0]), "+f"(d[1]), "+f"(d[2]), "+f"(d[3])
        : "r"(a[0]), "r"(a[1]), "r"(a[2]), "r"(a[3]), "r"(b0), "r"(b1));
}
__device__ __forceinline__ void cvt2(float x, float y, uint32_t& h, uint32_t& l) {
    __nv_bfloat162 hv, lv;
    hv.x = __float2bfloat16(x);
    hv.y = __float2bfloat16(y);
    lv.x = __float2bfloat16(x - __bfloat162float(hv.x));
    lv.y = __float2bfloat16(y - __bfloat162float(hv.y));
    h = *reinterpret_cast<uint32_t*>(&hv);
    l = *reinterpret_cast<uint32_t*>(&lv);
}
// cp.async 16B with optional zero-fill (src_size = 0 or 16)
__device__ __forceinline__ void cpa16(uint32_t dst, const void* src, int srcsize) {
    asm volatile("cp.async.cg.shared.global [%0], [%1], 16, %2;"
        :: "r"(dst), "l"(src), "r"(srcsize) : "memory");
}
__device__ __forceinline__ void cpa_commit() {
    asm volatile("cp.async.commit_group;" ::: "memory");
}
__device__ __forceinline__ void cpa_wait1() {
    asm volatile("cp.async.wait_group 1;" ::: "memory");
}
__device__ __forceinline__ void cpa_wait0() {
    asm volatile("cp.async.wait_group 0;" ::: "memory");
}

// ---------------------------------------------------------------------------
// Prep kernels: split fp32 -> bf16 hi/lo (same layouts as inputs)
// ---------------------------------------------------------------------------
__global__ void conv_emb_kernel(const float* __restrict__ emb) {
    int i = blockIdx.x * blockDim.x + threadIdx.x;     // over V_*I_/4 float4s
    float4 v = __ldg((const float4*)emb + i);
    uint32_t h0, l0, h1, l1;
    cvt2(v.x, v.y, h0, l0);
    cvt2(v.z, v.w, h1, l1);
    ((uint2*)g_emb_hi)[i] = make_uint2(h0, h1);
    ((uint2*)g_emb_lo)[i] = make_uint2(l0, l1);
}
__global__ void conv_w_kernel(const float* __restrict__ Wf, const float* __restrict__ Wi,
                              const float* __restrict__ Wg, const float* __restrict__ Wo) {
    int g = blockIdx.y;
    const float* W = (g == 0) ? Wf : (g == 1) ? Wi : (g == 2) ? Wg : Wo;
    int i = blockIdx.x * blockDim.x + threadIdx.x;     // over K_*H_/4 float4s
    float4 v = __ldg((const float4*)W + i);
    uint32_t h0, l0, h1, l1;
    cvt2(v.x, v.y, h0, l0);
    cvt2(v.z, v.w, h1, l1);
    ((uint2*)g_W_hi[g])[i] = make_uint2(h0, h1);
    ((uint2*)g_W_lo[g])[i] = make_uint2(l0, l1);
}

__global__ void init_kernel() {
    int i = blockIdx.x * blockDim.x + threadIdx.x;
    if (i < H_*B_) { g_hT[0][i] = 0.f; g_hT[1][i] = 0.f; }
}
__global__ void bar_reset_kernel() {
    if (threadIdx.x == 0 && blockIdx.x == 0) { g_bar_cnt = 0u; g_bar_gen = 0u; }
}

// ---------------------------------------------------------------------------
// Phase 1 (tensor cores): cp.async 2-stage pipeline, 2 blocks/SM.
// grid (4 n-tiles, 128 m-tiles, 4 gates); block 256; warp tile 64x32.
// 3-product bf16 split (hh + h*lo + lo*h), fp32 accum.
// ---------------------------------------------------------------------------
__global__ __launch_bounds__(256, 2) void pre_gemm_mma(const int* __restrict__ x)
{
    __shared__ int sx[128*16];

    const int tid  = threadIdx.x;
    const int m0   = blockIdx.y * 128;
    const int nb   = blockIdx.x * 128;
    const int gate = blockIdx.z;

    const __nv_bfloat16* Eh = g_emb_hi;
    const __nv_bfloat16* El = g_emb_lo;
    const __nv_bfloat16* Wh = g_W_hi[gate];
    const __nv_bfloat16* Wl = g_W_lo[gate];

    for (int lin = tid; lin < 2048; lin += 256) {
        int mm = lin >> 4, p = lin & 15;
        int m = m0 + mm;
        sx[mm*16 + p] = x[(m & 63)*4096 + p*256 + (m >> 6)];
    }
    __syncthreads();   // sx ready

    const int w = tid >> 5, lane = tid & 31;
    const int warp_m = (w & 1) * 64;
    const int warp_n = (w >> 1) * 32;

    // ldmatrix lane offsets
    const int am_off = lane & 15;
    const int ak_off = (lane >> 4) * 8;
    const int bk_off = ((lane >> 3) & 1)*8 + (lane & 7);
    const int bn_off = ((lane >> 4) & 1)*8;

    // cp.async chunk mappings (512 16B-chunks per table; 2 per thread)
    // A: chunk c -> row c>>2 (m), seg c&3 (8 bf16). B: row c>>4 (k), seg c&15.
    const int ar0 = tid >> 1,          aq0 = (tid & 1) * 2;      // chunks tid*2, tid*2+1
    const int br0 = tid >> 3,          bq0 = (tid & 7) * 2;

    // fill stage s with K-chunk ko (BK=32)
    auto fill = [&](int s, int ko) {
        char* st = dynsm + s * STAGE_BYTES;
        uint32_t ah_b = smem_u32(st);
        uint32_t al_b = ah_b + ABYTES;
        uint32_t bh_b = al_b + ABYTES;
        uint32_t bl_b = bh_b + BBYTES;
        const int p  = ko >> 3;
        const int i0 = (ko & 7) << 5;
        #pragma unroll
        for (int q = 0; q < 2; q++) {
            int row = ar0, seg = aq0 + q;                 // A row, 8-elem seg
            int idx = sx[row*16 + p];
            int sz  = idx ? 16 : 0;
            uint32_t doff = row*(ASTR*2) + seg*16;
            cpa16(ah_b + doff, Eh + (size_t)idx*I_ + i0 + seg*8, sz);
            cpa16(al_b + doff, El + (size_t)idx*I_ + i0 + seg*8, sz);
        }
        #pragma unroll
        for (int q = 0; q < 2; q++) {
            int row = br0, seg = bq0 + q;                 // B k-row, 8-elem seg
            uint32_t doff = row*(BSTR*2) + seg*16;
            const size_t soff = (size_t)(ko*32 + row)*H_ + nb + seg*8;
            cpa16(bh_b + doff, Wh + soff, 16);
            cpa16(bl_b + doff, Wl + soff, 16);
        }
        cpa_commit();
    };

    float acc[4][4][4];
    #pragma unroll
    for (int mi = 0; mi < 4; mi++)
        #pragma unroll
        for (int nt = 0; nt < 4; nt++)
            #pragma unroll
            for (int e = 0; e < 4; e++) acc[mi][nt][e] = 0.f;

    fill(0, 0);
    fill(1, 1);

    for (int ko = 0; ko < 128; ko++) {
        const int s = ko & 1;
        if (ko + 2 < 128) cpa_wait1(); else cpa_wait0();
        __syncthreads();                                   // stage s data visible

        char* st = dynsm + s * STAGE_BYTES;
        __nv_bfloat16* As_hi = (__nv_bfloat16*)st;
        __nv_bfloat16* As_lo = As_hi + 128*ASTR;
        __nv_bfloat16* Bs_hi = As_lo + 128*ASTR;
        __nv_bfloat16* Bs_lo = Bs_hi + 32*BSTR;

        #pragma unroll
        for (int ks = 0; ks < 2; ks++) {
            uint32_t ah[4][4], bh[8];
            #pragma unroll
            for (int mi = 0; mi < 4; mi++)
                ldsm_x4(ah[mi], smem_u32(As_hi + (warp_m + mi*16 + am_off)*ASTR
                                               + ks*16 + ak_off));
            #pragma unroll
            for (int j2 = 0; j2 < 2; j2++)
                ldsm_x4_t(&bh[j2*4], smem_u32(Bs_hi + (ks*16 + bk_off)*BSTR
                                                    + warp_n + j2*16 + bn_off));
            #pragma unroll
            for (int mi = 0; mi < 4; mi++)
                #pragma unroll
                for (int nt = 0; nt < 4; nt++)
                    mma_bf16(acc[mi][nt], ah[mi], bh[nt*2], bh[nt*2+1]);

            uint32_t bl[8];
            #pragma unroll
            for (int j2 = 0; j2 < 2; j2++)
                ldsm_x4_t(&bl[j2*4], smem_u32(Bs_lo + (ks*16 + bk_off)*BSTR
                                                    + warp_n + j2*16 + bn_off));
            #pragma unroll
            for (int mi = 0; mi < 4; mi++)
                #pragma unroll
                for (int nt = 0; nt < 4; nt++)
                    mma_bf16(acc[mi][nt], ah[mi], bl[nt*2], bl[nt*2+1]);

            uint32_t al[4];
            #pragma unroll
            for (int mi = 0; mi < 4; mi++) {
                ldsm_x4(al, smem_u32(As_lo + (warp_m + mi*16 + am_off)*ASTR
                                           + ks*16 + ak_off));
                #pragma unroll
                for (int nt = 0; nt < 4; nt++)
                    mma_bf16(acc[mi][nt], al, bh[nt*2], bh[nt*2+1]);
            }
        }
        __syncthreads();                                   // stage s fully consumed
        if (ko + 2 < 128) fill(s, ko + 2);
    }

    const int er = lane >> 2, ec = (lane & 3)*2;
    #pragma unroll
    for (int mi = 0; mi < 4; mi++)
        #pragma unroll
        for (int nt = 0; nt < 4; nt++) {
            int row = m0 + warp_m + mi*16 + er;
            int col = gate*H_ + nb + warp_n + nt*8 + ec;
            float2 v0 = make_float2(acc[mi][nt][0], acc[mi][nt][1]);
            float2 v1 = make_float2(acc[mi][nt][2], acc[mi][nt][3]);
            __stcs((float2*)&g_pre[(size_t)row * NCOL + col], v0);
            __stcs((float2*)&g_pre[(size_t)(row + 8) * NCOL + col], v1);
        }
}

// ---------------------------------------------------------------------------
// grid barrier (128 blocks co-resident)
// ---------------------------------------------------------------------------
__device__ __forceinline__ void grid_barrier() {
    __threadfence();
    __syncthreads();
    if (threadIdx.x == 0) {
        unsigned gen = *(volatile unsigned*)&g_bar_gen;
        if (atomicAdd(&g_bar_cnt, 1u) == NBLK - 1) {
            atomicExch(&g_bar_cnt, 0u);
            atomicAdd(&g_bar_gen, 1u);
        } else {
            unsigned cur;
            do {
                __nanosleep(64);
                asm volatile("ld.global.acquire.gpu.u32 %0, [%1];"
                             : "=r"(cur) : "l"(&g_bar_gen));
            } while (cur == gen);
        }
        __threadfence();
    }
    __syncthreads();
}

// ---------------------------------------------------------------------------
// Phase 2: persistent recurrence (unchanged)
// ---------------------------------------------------------------------------
__global__ __launch_bounds__(512, 1) void lstm_persist_kernel(
    const float* __restrict__ Wfh, const float* __restrict__ Wih,
    const float* __restrict__ Wgh, const float* __restrict__ Woh,
    const float* __restrict__ bf,  const float* __restrict__ bi,
    const float* __restrict__ bg,  const float* __restrict__ bo)
{
    unsigned long long* ws2 = (unsigned long long*)dynsm;       // [512][16] dup f32x2
    float4* hbuf = (float4*)(dynsm + 65536);                    // 4 x [2048] float4
    float*  sg   = (float*)(dynsm + 65536 + 131072);            // 2 x [64][17]

    const int tid  = threadIdx.x;
    const int kh   = tid >> 8;
    const int stid = tid & 255;
    const int tx   = stid & 15;
    const int ty   = stid >> 4;
    const int hc0  = blockIdx.x * 4;

    for (int idx = tid; idx < 512*16; idx += 512) {
        int k = idx >> 4, c = idx & 15;
        int g = c >> 2;
        const float* Wp = (g == 0) ? Wfh : (g == 1) ? Wih : (g == 2) ? Wgh : Woh;
        float wv = Wp[k*H_ + hc0 + (c & 3)];
        float2 w2 = make_float2(wv, wv);
        ws2[idx] = *reinterpret_cast<unsigned long long*>(&w2);
    }

    const int pb  = stid >> 2, pj = stid & 3;
    const int phc = hc0 + pj;
    const float bfv = bf[phc], biv = bi[phc], bgv = bg[phc], bov = bo[phc];
    const float* preb = g_pre + (size_t)pb * NCOL + phc;
    float creg = 0.f;

    __syncthreads();

    for (int t = 0; t < T_; t++) {
        const int cur = t & 1, nxt = cur ^ 1;

        float pf, pi, pg, po;
        if (kh == 0) {
            const float* pp = preb + (size_t)t * 64 * NCOL;
            pf = __ldcs(pp);
            pi = __ldcs(pp + 512);
            pg = __ldcs(pp + 1024);
            po = __ldcs(pp + 1536);
        }

        const float4* h4 = (const float4*)g_hT[cur];
        unsigned long long acc0 = 0ULL, acc1 = 0ULL, acc2 = 0ULL, acc3 = 0ULL;

        float4 r[8];
        {
            const float4* src = h4 + (kh*2) * 2048 + stid;
            #pragma unroll
            for (int q = 0; q < 8; q++) r[q] = __ldcg(src + q*256);
        }

        #pragma unroll
        for (int cc = 0; cc < 2; cc++) {
            const int c = kh*2 + cc;
            float4* bufp = hbuf + (size_t)(kh*2 + cc) * 2048;
            #pragma unroll
            for (int q = 0; q < 8; q++) bufp[stid + q*256] = r[q];
            __syncthreads();
            if (cc == 0) {
                const float4* src = h4 + (kh*2 + 1) * 2048 + stid;
                #pragma unroll
                for (int q = 0; q < 8; q++) r[q] = __ldcg(src + q*256);
            }
            const ulonglong2* hb = (const ulonglong2*)bufp;
            const unsigned long long* wsb = ws2 + (size_t)c * 128 * 16;
            #pragma unroll 8
            for (int kk = 0; kk < 128; kk++) {
                ulonglong2 a = hb[kk*16 + ty];
                unsigned long long wv = wsb[kk*16 + tx];
                if (kk & 1) { ffma2(acc2, a.x, wv); ffma2(acc3, a.y, wv); }
                else        { ffma2(acc0, a.x, wv); ffma2(acc1, a.y, wv); }
            }
            __syncthreads();
        }

        float2 e0 = u2f(acc0), o0 = u2f(acc2), e1 = u2f(acc1), o1 = u2f(acc3);
        float* sgh = sg + kh * (64*17);
        sgh[(4*ty + 0)*17 + tx] = e0.x + o0.x;
        sgh[(4*ty + 1)*17 + tx] = e0.y + o0.y;
        sgh[(4*ty + 2)*17 + tx] = e1.x + o1.x;
        sgh[(4*ty + 3)*17 + tx] = e1.y + o1.y;
        __syncthreads();

        if (kh == 0) {
            float f  = sigm(pf + bfv + sg[pb*17 + pj]        + sg[64*17 + pb*17 + pj]);
            float ii = sigm(pi + biv + sg[pb*17 + 4 + pj]    + sg[64*17 + pb*17 + 4 + pj]);
            float gg = tanhf(pg + bgv + sg[pb*17 + 8 + pj]   + sg[64*17 + pb*17 + 8 + pj]);
            float oo = sigm(po + bov + sg[pb*17 + 12 + pj]   + sg[64*17 + pb*17 + 12 + pj]);
            float cn = f * creg + ii * gg;
            float hn = oo * tanhf(cn);
            creg = cn;
            __stcg(&g_hT[nxt][phc*64 + pb], hn);
            if (t == T_ - 1) g_cfin[pb*H_ + phc] = cn;
        }

        if (t < T_ - 1) grid_barrier();
    }
}

// ---------------------------------------------------------------------------
// Phase 3: out = h_T @ W_lin + b_lin; emit (out, h_t, c_t)
// ---------------------------------------------------------------------------
__global__ void final_kernel(const float* __restrict__ Wlin,
                             const float* __restrict__ blin,
                             float* __restrict__ out)
{
    int b = blockIdx.x;
    int tid = threadIdx.x;  // 512
    __shared__ float sh[H_];
    float hv = g_hT[0][tid*64 + b];
    sh[tid] = hv;
    out[B_*O_ + b*H_ + tid]          = hv;
    out[B_*O_ + B_*H_ + b*H_ + tid]  = g_cfin[b*H_ + tid];
    __syncthreads();
    if (tid < O_) {
        float s = blin[tid];
        for (int k = 0; k < H_; k++) s += sh[k] * Wlin[k*O_ + tid];
        out[b*O_ + tid] = s;
    }
}

// ---------------------------------------------------------------------------
extern "C" void kernel_launch(void* const* d_in, const int* in_sizes, int n_in,
                              void* d_out, int out_size)
{
    const int*   x    = (const int*)  d_in[0];
    const float* emb  = (const float*)d_in[1];
    const float* Wfx  = (const float*)d_in[2];
    const float* Wfh  = (const float*)d_in[3];
    const float* bf   = (const float*)d_in[4];
    const float* Wix  = (const float*)d_in[5];
    const float* Wih  = (const float*)d_in[6];
    const float* bi   = (const float*)d_in[7];
    const float* Wgx  = (const float*)d_in[8];
    const float* Wgh  = (const float*)d_in[9];
    const float* bg   = (const float*)d_in[10];
    const float* Wox  = (const float*)d_in[11];
    const float* Woh  = (const float*)d_in[12];
    const float* bo   = (const float*)d_in[13];
    const float* Wlin = (const float*)d_in[14];
    const float* blin = (const float*)d_in[15];
    float* out = (float*)d_out;

    const int mma_dyn = 2 * STAGE_BYTES;   // 92160
    cudaFuncSetAttribute(pre_gemm_mma,
                         cudaFuncAttributeMaxDynamicSharedMemorySize, mma_dyn);

    conv_emb_kernel<<<V_*I_/4/256, 256>>>(emb);                        // 1
    conv_w_kernel<<<dim3(K_*H_/4/256, 4), 256>>>(Wfx, Wix, Wgx, Wox);  // 2
    init_kernel<<<(H_*B_ + 255)/256, 256>>>();                         // 3

    dim3 gfull(4, 128, 4);  // n-tiles x m-tiles x gates
    pre_gemm_mma<<<gfull, 256, mma_dyn>>>(x);                          // 4

    bar_reset_kernel<<<1, 32>>>();                                     // 5

    cudaFuncSetAttribute(lstm_persist_kernel,
                         cudaFuncAttributeMaxDynamicSharedMemorySize, 205312);
    lstm_persist_kernel<<<NBLK, 512, 205312>>>(Wfh, Wih, Wgh, Woh,     // 6 <- ncu
                                               bf, bi, bg, bo);

    final_kernel<<<B_, H_>>>(Wlin, blin, out);                         // 7
}

// round 16
// speedup vs baseline: 4.7275x; 1.0097x over previous
#include <cuda_runtime.h>
#include <cuda_bf16.h>
#include <cstdint>
#include <stdint.h>
#include <math.h>

#define B_   64
#define P_   16
#define T_   256
#define I_   256
#define H_   512
#define O_   5
#define V_   50000
#define NCOL 2048            // 4 gates * H
#define M_   (T_*B_)         // 16384 rows (t-major, b-minor)
#define K_   (P_*I_)         // 4096
#define NBLK 128             // persistent blocks for recurrence

#define ASTR 56              // A smem row stride (bf16 elems): 112B, 16B-aligned
#define BSTR 136             // B smem row stride: 272B, 16B-aligned
#define ABYTES (128*ASTR*2)  // 14336 per table
#define BBYTES (32*BSTR*2)   // 8704 per table
#define STAGE_BYTES (2*ABYTES + 2*BBYTES)   // 46080

// Scratch (static __device__ — no allocations allowed)
__device__ float g_pre[(size_t)M_ * NCOL];    // 134 MB gate pre-activations
__device__ float g_hT[2][H_ * B_];            // transposed hidden state [hcol][b]
__device__ float g_cfin[B_ * H_];             // final cell state
__device__ unsigned g_bar_gen;
__device__ unsigned g_bar_cnt;

// pre-split bf16 tables (filled once per run by prep kernels)
__device__ __nv_bfloat16 g_emb_hi[(size_t)V_ * I_];   // [V][I]
__device__ __nv_bfloat16 g_emb_lo[(size_t)V_ * I_];
__device__ __nv_bfloat16 g_W_hi[4][(size_t)K_ * H_];  // [gate][k][n]
__device__ __nv_bfloat16 g_W_lo[4][(size_t)K_ * H_];

extern __shared__ char dynsm[];               // shared by dynamic-smem kernels

// ---------------------------------------------------------------------------
__device__ __forceinline__ void ffma2(unsigned long long& acc,
                                      unsigned long long a, unsigned long long b) {
    asm("fma.rn.f32x2 %0, %1, %2, %0;" : "+l"(acc) : "l"(a), "l"(b));
}
__device__ __forceinline__ float2 u2f(unsigned long long u) {
    union { unsigned long long u; float2 f; } v; v.u = u; return v.f;
}
__device__ __forceinline__ float sigm(float v) { return 1.f / (1.f + expf(-v)); }

__device__ __forceinline__ uint32_t smem_u32(const void* p) {
    return (uint32_t)__cvta_generic_to_shared(p);
}
__device__ __forceinline__ void ldsm_x4(uint32_t* r, uint32_t addr) {
    asm volatile("ldmatrix.sync.aligned.m8n8.x4.shared.b16 {%0,%1,%2,%3}, [%4];"
        : "=r"(r[0]), "=r"(r[1]), "=r"(r[2]), "=r"(r[3]) : "r"(addr));
}
__device__ __forceinline__ void ldsm_x4_t(uint32_t* r, uint32_t addr) {
    asm volatile("ldmatrix.sync.aligned.m8n8.x4.trans.shared.b16 {%0,%1,%2,%3}, [%4];"
        : "=r"(r[0]), "=r"(r[1]), "=r"(r[2]), "=r"(r[3]) : "r"(addr));
}
__device__ __forceinline__ void mma_bf16(float* d, const uint32_t* a,
                                         uint32_t b0, uint32_t b1) {
    asm volatile("mma.sync.aligned.m16n8k16.row.col.f32.bf16.bf16.f32 "
        "{%0,%1,%2,%3}, {%4,%5,%6,%7}, {%8,%9}, {%0,%1,%2,%3};"
        : "+f"(d[0]), "+f"(d[1]), "+f"(d[2]), "+f"(d[3])
        : "r"(a[0]), "r"(a[1]), "r"(a[2]), "r"(a[3]), "r"(b0), "r"(b1));
}
__device__ __forceinline__ void cvt2(float x, float y, uint32_t& h, uint32_t& l) {
    __nv_bfloat162 hv, lv;
    hv.x = __float2bfloat16(x);
    hv.y = __float2bfloat16(y);
    lv.x = __float2bfloat16(x - __bfloat162float(hv.x));
    lv.y = __float2bfloat16(y - __bfloat162float(hv.y));
    h = *reinterpret_cast<uint32_t*>(&hv);
    l = *reinterpret_cast<uint32_t*>(&lv);
}
// cp.async 16B with optional zero-fill (src_size = 0 or 16)
__device__ __forceinline__ void cpa16(uint32_t dst, const void* src, int srcsize) {
    asm volatile("cp.async.cg.shared.global [%0], [%1], 16, %2;"
        :: "r"(dst), "l"(src), "r"(srcsize) : "memory");
}
__device__ __forceinline__ void cpa_commit() {
    asm volatile("cp.async.commit_group;" ::: "memory");
}
__device__ __forceinline__ void cpa_wait1() {
    asm volatile("cp.async.wait_group 1;" ::: "memory");
}
__device__ __forceinline__ void cpa_wait0() {
    asm volatile("cp.async.wait_group 0;" ::: "memory");
}

// ---------------------------------------------------------------------------
// Prep kernels: split fp32 -> bf16 hi/lo (same layouts as inputs)
// ---------------------------------------------------------------------------
__global__ void conv_emb_kernel(const float* __restrict__ emb) {
    int i = blockIdx.x * blockDim.x + threadIdx.x;     // over V_*I_/4 float4s
    float4 v = __ldg((const float4*)emb + i);
    uint32_t h0, l0, h1, l1;
    cvt2(v.x, v.y, h0, l0);
    cvt2(v.z, v.w, h1, l1);
    ((uint2*)g_emb_hi)[i] = make_uint2(h0, h1);
    ((uint2*)g_emb_lo)[i] = make_uint2(l0, l1);
}
__global__ void conv_w_kernel(const float* __restrict__ Wf, const float* __restrict__ Wi,
                              const float* __restrict__ Wg, const float* __restrict__ Wo) {
    int g = blockIdx.y;
    const float* W = (g == 0) ? Wf : (g == 1) ? Wi : (g == 2) ? Wg : Wo;
    int i = blockIdx.x * blockDim.x + threadIdx.x;     // over K_*H_/4 float4s
    float4 v = __ldg((const float4*)W + i);
    uint32_t h0, l0, h1, l1;
    cvt2(v.x, v.y, h0, l0);
    cvt2(v.z, v.w, h1, l1);
    ((uint2*)g_W_hi[g])[i] = make_uint2(h0, h1);
    ((uint2*)g_W_lo[g])[i] = make_uint2(l0, l1);
}

__global__ void init_kernel() {
    int i = blockIdx.x * blockDim.x + threadIdx.x;
    if (i < H_*B_) { g_hT[0][i] = 0.f; g_hT[1][i] = 0.f; }
}
__global__ void bar_reset_kernel() {
    if (threadIdx.x == 0 && blockIdx.x == 0) { g_bar_cnt = 0u; g_bar_gen = 0u; }
}

// ---------------------------------------------------------------------------
// Phase 1 (tensor cores): cp.async 2-stage pipeline, 2 blocks/SM (unchanged).
// ---------------------------------------------------------------------------
__global__ __launch_bounds__(256, 2) void pre_gemm_mma(const int* __restrict__ x)
{
    __shared__ int sx[128*16];

    const int tid  = threadIdx.x;
    const int m0   = blockIdx.y * 128;
    const int nb   = blockIdx.x * 128;
    const int gate = blockIdx.z;

    const __nv_bfloat16* Eh = g_emb_hi;
    const __nv_bfloat16* El = g_emb_lo;
    const __nv_bfloat16* Wh = g_W_hi[gate];
    const __nv_bfloat16* Wl = g_W_lo[gate];

    for (int lin = tid; lin < 2048; lin += 256) {
        int mm = lin >> 4, p = lin & 15;
        int m = m0 + mm;
        sx[mm*16 + p] = x[(m & 63)*4096 + p*256 + (m >> 6)];
    }
    __syncthreads();   // sx ready

    const int w = tid >> 5, lane = tid & 31;
    const int warp_m = (w & 1) * 64;
    const int warp_n = (w >> 1) * 32;

    const int am_off = lane & 15;
    const int ak_off = (lane >> 4) * 8;
    const int bk_off = ((lane >> 3) & 1)*8 + (lane & 7);
    const int bn_off = ((lane >> 4) & 1)*8;

    const int ar0 = tid >> 1,          aq0 = (tid & 1) * 2;
    const int br0 = tid >> 3,          bq0 = (tid & 7) * 2;

    auto fill = [&](int s, int ko) {
        char* st = dynsm + s * STAGE_BYTES;
        uint32_t ah_b = smem_u32(st);
        uint32_t al_b = ah_b + ABYTES;
        uint32_t bh_b = al_b + ABYTES;
        uint32_t bl_b = bh_b + BBYTES;
        const int p  = ko >> 3;
        const int i0 = (ko & 7) << 5;
        #pragma unroll
        for (int q = 0; q < 2; q++) {
            int row = ar0, seg = aq0 + q;
            int idx = sx[row*16 + p];
            int sz  = idx ? 16 : 0;
            uint32_t doff = row*(ASTR*2) + seg*16;
            cpa16(ah_b + doff, Eh + (size_t)idx*I_ + i0 + seg*8, sz);
            cpa16(al_b + doff, El + (size_t)idx*I_ + i0 + seg*8, sz);
        }
        #pragma unroll
        for (int q = 0; q < 2; q++) {
            int row = br0, seg = bq0 + q;
            uint32_t doff = row*(BSTR*2) + seg*16;
            const size_t soff = (size_t)(ko*32 + row)*H_ + nb + seg*8;
            cpa16(bh_b + doff, Wh + soff, 16);
            cpa16(bl_b + doff, Wl + soff, 16);
        }
        cpa_commit();
    };

    float acc[4][4][4];
    #pragma unroll
    for (int mi = 0; mi < 4; mi++)
        #pragma unroll
        for (int nt = 0; nt < 4; nt++)
            #pragma unroll
            for (int e = 0; e < 4; e++) acc[mi][nt][e] = 0.f;

    fill(0, 0);
    fill(1, 1);

    for (int ko = 0; ko < 128; ko++) {
        const int s = ko & 1;
        if (ko + 2 < 128) cpa_wait1(); else cpa_wait0();
        __syncthreads();

        char* st = dynsm + s * STAGE_BYTES;
        __nv_bfloat16* As_hi = (__nv_bfloat16*)st;
        __nv_bfloat16* As_lo = As_hi + 128*ASTR;
        __nv_bfloat16* Bs_hi = As_lo + 128*ASTR;
        __nv_bfloat16* Bs_lo = Bs_hi + 32*BSTR;

        #pragma unroll
        for (int ks = 0; ks < 2; ks++) {
            uint32_t ah[4][4], bh[8];
            #pragma unroll
            for (int mi = 0; mi < 4; mi++)
                ldsm_x4(ah[mi], smem_u32(As_hi + (warp_m + mi*16 + am_off)*ASTR
                                               + ks*16 + ak_off));
            #pragma unroll
            for (int j2 = 0; j2 < 2; j2++)
                ldsm_x4_t(&bh[j2*4], smem_u32(Bs_hi + (ks*16 + bk_off)*BSTR
                                                    + warp_n + j2*16 + bn_off));
            #pragma unroll
            for (int mi = 0; mi < 4; mi++)
                #pragma unroll
                for (int nt = 0; nt < 4; nt++)
                    mma_bf16(acc[mi][nt], ah[mi], bh[nt*2], bh[nt*2+1]);

            uint32_t bl[8];
            #pragma unroll
            for (int j2 = 0; j2 < 2; j2++)
                ldsm_x4_t(&bl[j2*4], smem_u32(Bs_lo + (ks*16 + bk_off)*BSTR
                                                    + warp_n + j2*16 + bn_off));
            #pragma unroll
            for (int mi = 0; mi < 4; mi++)
                #pragma unroll
                for (int nt = 0; nt < 4; nt++)
                    mma_bf16(acc[mi][nt], ah[mi], bl[nt*2], bl[nt*2+1]);

            uint32_t al[4];
            #pragma unroll
            for (int mi = 0; mi < 4; mi++) {
                ldsm_x4(al, smem_u32(As_lo + (warp_m + mi*16 + am_off)*ASTR
                                           + ks*16 + ak_off));
                #pragma unroll
                for (int nt = 0; nt < 4; nt++)
                    mma_bf16(acc[mi][nt], al, bh[nt*2], bh[nt*2+1]);
            }
        }
        __syncthreads();
        if (ko + 2 < 128) fill(s, ko + 2);
    }

    const int er = lane >> 2, ec = (lane & 3)*2;
    #pragma unroll
    for (int mi = 0; mi < 4; mi++)
        #pragma unroll
        for (int nt = 0; nt < 4; nt++) {
            int row = m0 + warp_m + mi*16 + er;
            int col = gate*H_ + nb + warp_n + nt*8 + ec;
            float2 v0 = make_float2(acc[mi][nt][0], acc[mi][nt][1]);
            float2 v1 = make_float2(acc[mi][nt][2], acc[mi][nt][3]);
            __stcs((float2*)&g_pre[(size_t)row * NCOL + col], v0);
            __stcs((float2*)&g_pre[(size_t)(row + 8) * NCOL + col], v1);
        }
}

// ---------------------------------------------------------------------------
// grid barrier (128 blocks co-resident)
// ---------------------------------------------------------------------------
__device__ __forceinline__ void grid_barrier() {
    __threadfence();
    __syncthreads();
    if (threadIdx.x == 0) {
        unsigned gen = *(volatile unsigned*)&g_bar_gen;
        if (atomicAdd(&g_bar_cnt, 1u) == NBLK - 1) {
            atomicExch(&g_bar_cnt, 0u);
            atomicAdd(&g_bar_gen, 1u);
        } else {
            unsigned cur;
            do {
                __nanosleep(32);
                asm volatile("ld.global.acquire.gpu.u32 %0, [%1];"
                             : "=r"(cur) : "l"(&g_bar_gen));
            } while (cur == gen);
        }
        __threadfence();
    }
    __syncthreads();
}

// ---------------------------------------------------------------------------
// Phase 2: persistent recurrence — restructured step:
//  * all 16 h-chunk LDG.128 front-batched (MLP=16) right after barrier
//  * ONE staging sync, then GEMV over this half's contiguous 256-k range
//  * paired dup-weight layout: one LDS.128 feeds two k-steps (7 instr / 2k)
// smem: wsp 64KB | hbuf 128KB | sg 2x(64x17)f  -> 205312 B total (1 block/SM)
// ---------------------------------------------------------------------------
__global__ __launch_bounds__(512, 1) void lstm_persist_kernel(
    const float* __restrict__ Wfh, const float* __restrict__ Wih,
    const float* __restrict__ Wgh, const float* __restrict__ Woh,
    const float* __restrict__ bf,  const float* __restrict__ bi,
    const float* __restrict__ bg,  const float* __restrict__ bo)
{
    unsigned long long* wsp = (unsigned long long*)dynsm;       // paired dup weights
    float4* hbuf = (float4*)(dynsm + 65536);                    // full h [k][b], 128KB
    float*  sg   = (float*)(dynsm + 65536 + 131072);            // 2 x [64][17]

    const int tid  = threadIdx.x;
    const int kh   = tid >> 8;          // k-half: 0 -> k[0,256), 1 -> k[256,512)
    const int stid = tid & 255;
    const int tx   = stid & 15;         // col: gate = tx>>2, hj = tx&3
    const int ty   = stid >> 4;         // batch group: b = 4*ty .. 4*ty+3
    const int hc0  = blockIdx.x * 4;

    // paired weight fill: wsp_ull[((k>>1)*16 + c)*2 + (k&1)] = dup(W[k][col])
    for (int idx = tid; idx < 512*16; idx += 512) {
        int k = idx >> 4, c = idx & 15;
        int g = c >> 2;
        const float* Wp = (g == 0) ? Wfh : (g == 1) ? Wih : (g == 2) ? Wgh : Woh;
        float wv = Wp[k*H_ + hc0 + (c & 3)];
        float2 w2 = make_float2(wv, wv);
        wsp[((k >> 1)*16 + c)*2 + (k & 1)] = *reinterpret_cast<unsigned long long*>(&w2);
    }

    const int pb  = stid >> 2, pj = stid & 3;
    const int phc = hc0 + pj;
    const float bfv = bf[phc], biv = bi[phc], bgv = bg[phc], bov = bo[phc];
    const float* preb = g_pre + (size_t)pb * NCOL + phc;
    float creg = 0.f;

    __syncthreads();

    for (int t = 0; t < T_; t++) {
        const int cur = t & 1, nxt = cur ^ 1;

        // streaming pre-activation loads (DRAM; hidden under the GEMV)
        float pf, pi, pg, po;
        if (kh == 0) {
            const float* pp = preb + (size_t)t * 64 * NCOL;
            pf = __ldcs(pp);
            pi = __ldcs(pp + 512);
            pg = __ldcs(pp + 1024);
            po = __ldcs(pp + 1536);
        }

        // front-batch ALL h loads for this half (16 x LDG.128, MLP=16)
        const float4* src = (const float4*)g_hT[cur] + kh*4096 + stid;
        float4 r[16];
        #pragma unroll
        for (int q = 0; q < 16; q++) r[q] = __ldcg(src + q*256);
        float4* buf = hbuf + kh*4096;
        #pragma unroll
        for (int q = 0; q < 16; q++) buf[stid + q*256] = r[q];
        __syncthreads();

        // GEMV over this half's 256 k (128 paired steps)
        const ulonglong2* hb = (const ulonglong2*)(hbuf + kh*4096);
        const ulonglong2* wp = (const ulonglong2*)wsp + (size_t)kh*128*16;
        unsigned long long acc0 = 0ULL, acc1 = 0ULL, acc2 = 0ULL, acc3 = 0ULL;
        #pragma unroll 8
        for (int kk2 = 0; kk2 < 128; kk2++) {
            ulonglong2 w2 = wp[kk2*16 + tx];          // {dup w(2k), dup w(2k+1)}
            ulonglong2 a0 = hb[(2*kk2)*16 + ty];      // even k, 4 batches
            ulonglong2 a1 = hb[(2*kk2 + 1)*16 + ty];  // odd  k, 4 batches
            ffma2(acc0, a0.x, w2.x); ffma2(acc1, a0.y, w2.x);
            ffma2(acc2, a1.x, w2.y); ffma2(acc3, a1.y, w2.y);
        }

        float2 e0 = u2f(acc0), o0 = u2f(acc2), e1 = u2f(acc1), o1 = u2f(acc3);
        float* sgh = sg + kh * (64*17);
        sgh[(4*ty + 0)*17 + tx] = e0.x + o0.x;
        sgh[(4*ty + 1)*17 + tx] = e0.y + o0.y;
        sgh[(4*ty + 2)*17 + tx] = e1.x + o1.x;
        sgh[(4*ty + 3)*17 + tx] = e1.y + o1.y;
        __syncthreads();

        if (kh == 0) {
            float f  = sigm(pf + bfv + sg[pb*17 + pj]        + sg[64*17 + pb*17 + pj]);
            float ii = sigm(pi + biv + sg[pb*17 + 4 + pj]    + sg[64*17 + pb*17 + 4 + pj]);
            float gg = tanhf(pg + bgv + sg[pb*17 + 8 + pj]   + sg[64*17 + pb*17 + 8 + pj]);
            float oo = sigm(po + bov + sg[pb*17 + 12 + pj]   + sg[64*17 + pb*17 + 12 + pj]);
            float cn = f * creg + ii * gg;
            float hn = oo * tanhf(cn);
            creg = cn;
            __stcg(&g_hT[nxt][phc*64 + pb], hn);
            if (t == T_ - 1) g_cfin[pb*H_ + phc] = cn;
        }

        if (t < T_ - 1) grid_barrier();
    }
}

// ---------------------------------------------------------------------------
// Phase 3: out = h_T @ W_lin + b_lin; emit (out, h_t, c_t)
// ---------------------------------------------------------------------------
__global__ void final_kernel(const float* __restrict__ Wlin,
                             const float* __restrict__ blin,
                             float* __restrict__ out)
{
    int b = blockIdx.x;
    int tid = threadIdx.x;  // 512
    __shared__ float sh[H_];
    float hv = g_hT[0][tid*64 + b];
    sh[tid] = hv;
    out[B_*O_ + b*H_ + tid]          = hv;
    out[B_*O_ + B_*H_ + b*H_ + tid]  = g_cfin[b*H_ + tid];
    __syncthreads();
    if (tid < O_) {
        float s = blin[tid];
        for (int k = 0; k < H_; k++) s += sh[k] * Wlin[k*O_ + tid];
        out[b*O_ + tid] = s;
    }
}

// ---------------------------------------------------------------------------
extern "C" void kernel_launch(void* const* d_in, const int* in_sizes, int n_in,
                              void* d_out, int out_size)
{
    const int*   x    = (const int*)  d_in[0];
    const float* emb  = (const float*)d_in[1];
    const float* Wfx  = (const float*)d_in[2];
    const float* Wfh  = (const float*)d_in[3];
    const float* bf   = (const float*)d_in[4];
    const float* Wix  = (const float*)d_in[5];
    const float* Wih  = (const float*)d_in[6];
    const float* bi   = (const float*)d_in[7];
    const float* Wgx  = (const float*)d_in[8];
    const float* Wgh  = (const float*)d_in[9];
    const float* bg   = (const float*)d_in[10];
    const float* Wox  = (const float*)d_in[11];
    const float* Woh  = (const float*)d_in[12];
    const float* bo   = (const float*)d_in[13];
    const float* Wlin = (const float*)d_in[14];
    const float* blin = (const float*)d_in[15];
    float* out = (float*)d_out;

    const int mma_dyn = 2 * STAGE_BYTES;   // 92160
    cudaFuncSetAttribute(pre_gemm_mma,
                         cudaFuncAttributeMaxDynamicSharedMemorySize, mma_dyn);

    conv_emb_kernel<<<V_*I_/4/256, 256>>>(emb);                        // 1
    conv_w_kernel<<<dim3(K_*H_/4/256, 4), 256>>>(Wfx, Wix, Wgx, Wox);  // 2
    init_kernel<<<(H_*B_ + 255)/256, 256>>>();                         // 3

    dim3 gfull(4, 128, 4);  // n-tiles x m-tiles x gates
    pre_gemm_mma<<<gfull, 256, mma_dyn>>>(x);                          // 4

    bar_reset_kernel<<<1, 32>>>();                                     // 5

    cudaFuncSetAttribute(lstm_persist_kernel,
                         cudaFuncAttributeMaxDynamicSharedMemorySize, 205312);
    lstm_persist_kernel<<<NBLK, 512, 205312>>>(Wfh, Wih, Wgh, Woh,     // 6 <- ncu
                                               bf, bi, bg, bo);

    final_kernel<<<B_, H_>>>(Wlin, blin, out);                         // 7
}